// round 6
// baseline (speedup 1.0000x reference)
#include <cuda_runtime.h>
#include <cuda_fp16.h>
#include <math_constants.h>
#include <cstdint>

// Problem constants (fixed by the dataset)
#define NN   50000
#define EE   600000
#define GG   1000
#define HID  128
#define INF_ 64
#define EPS  1e-5f
#define SLOPE 0.01f

#define NB_SCAN ((NN + 255) / 256)

// ---------------------------------------------------------------------------
// Scratch (static __device__ arrays; no allocation anywhere)
// ---------------------------------------------------------------------------
__device__ __half g_hs [NN * HID];    // x@W in fp16 (no cs), gather source
__device__ float  g_ya [NN * HID];    // y triple buffer (layer 0)
__device__ float  g_yb [NN * HID];    // (layer 1)
__device__ float  g_yc [NN * HID];    // (layer 2)
__device__ float  g_cs [NN];
__device__ float  g_cd [NN];
__device__ int    g_deg[2 * NN];
__device__ int    g_csr_start[NN + 1];
__device__ int    g_cursor[NN];
__device__ int    g_csr_src[EE];
__device__ int    g_bsum[256];
__device__ float  g_stats[3 * 2 * HID];
__device__ int    g_gstart[GG + 1];

__device__ __forceinline__ float leaky(float v) { return v > 0.f ? v : SLOPE * v; }

// alpha/beta for channel c from this layer's stats + gn params
__device__ __forceinline__ void alpha_beta(const float* __restrict__ stats,
                                           const float* __restrict__ gw,
                                           const float* __restrict__ gb,
                                           const float* __restrict__ gs,
                                           int c, float& a, float& b) {
    float m   = stats[c] * (1.f / (float)NN);
    float ex2 = stats[HID + c] * (1.f / (float)NN);
    float s   = gs[c];
    float var = ex2 - m * m * (2.f * s - s * s);
    float inv = rsqrtf(var + EPS);
    a = inv * gw[c];
    b = gb[c] - s * m * a;
}

// ---------------------------------------------------------------------------
// Setup zero: deg + stats
// ---------------------------------------------------------------------------
__global__ void k_setup_zero(int* __restrict__ deg, float* __restrict__ stats) {
    int i = blockIdx.x * blockDim.x + threadIdx.x;
    int stride = gridDim.x * blockDim.x;
    for (int j = i; j < 2 * NN; j += stride) deg[j] = 0;
    for (int j = i; j < 3 * 2 * HID; j += stride) stats[j] = 0.f;
}

// ---------------------------------------------------------------------------
// Degrees
// ---------------------------------------------------------------------------
__global__ void k_degrees(const int* __restrict__ src, const int* __restrict__ dst,
                          int* __restrict__ deg) {
    int e = blockIdx.x * blockDim.x + threadIdx.x;
    if (e >= EE) return;
    atomicAdd(&deg[src[e]], 1);
    atomicAdd(&deg[NN + dst[e]], 1);
}

__global__ void k_invdeg(const int* __restrict__ deg,
                         float* __restrict__ cs, float* __restrict__ cd) {
    int i = blockIdx.x * blockDim.x + threadIdx.x;
    if (i >= NN) return;
    cs[i] = rsqrtf(fmaxf((float)deg[i], 1.f));
    cd[i] = rsqrtf(fmaxf((float)deg[NN + i], 1.f));
}

// ---------------------------------------------------------------------------
// Graph segment starts (graph_ids sorted ascending)
// ---------------------------------------------------------------------------
__global__ void k_gstart(const int* __restrict__ gid, int* __restrict__ gstart) {
    int i = blockIdx.x * blockDim.x + threadIdx.x;
    if (i >= NN) return;
    int g  = gid[i];
    int gp = (i == 0) ? -1 : gid[i - 1];
    for (int gg = gp + 1; gg <= g; gg++) gstart[gg] = i;
    if (i == NN - 1)
        for (int gg = g + 1; gg <= GG; gg++) gstart[gg] = NN;
}

// ---------------------------------------------------------------------------
// CSR-by-dst build (3-step scan + fill)
// ---------------------------------------------------------------------------
__global__ void k_scan1(const int* __restrict__ indeg, int* __restrict__ bsum) {
    __shared__ int sh[256];
    int i = blockIdx.x * 256 + threadIdx.x;
    sh[threadIdx.x] = (i < NN) ? indeg[i] : 0;
    __syncthreads();
    for (int o = 128; o > 0; o >>= 1) {
        if (threadIdx.x < o) sh[threadIdx.x] += sh[threadIdx.x + o];
        __syncthreads();
    }
    if (threadIdx.x == 0) bsum[blockIdx.x] = sh[0];
}

__global__ void k_scan2(int* __restrict__ bsum) {
    __shared__ int sh[256];
    int tid = threadIdx.x;
    int v = (tid < NB_SCAN) ? bsum[tid] : 0;
    sh[tid] = v;
    __syncthreads();
    for (int o = 1; o < 256; o <<= 1) {
        int t = (tid >= o) ? sh[tid - o] : 0;
        __syncthreads();
        sh[tid] += t;
        __syncthreads();
    }
    if (tid < NB_SCAN) bsum[tid] = sh[tid] - v;
}

__global__ void k_scan3(const int* __restrict__ indeg, const int* __restrict__ bsum,
                        int* __restrict__ csr_start, int* __restrict__ cursor) {
    __shared__ int sh[256];
    int tid = threadIdx.x;
    int i = blockIdx.x * 256 + tid;
    int v = (i < NN) ? indeg[i] : 0;
    sh[tid] = v;
    __syncthreads();
    for (int o = 1; o < 256; o <<= 1) {
        int t = (tid >= o) ? sh[tid - o] : 0;
        __syncthreads();
        sh[tid] += t;
        __syncthreads();
    }
    int excl = sh[tid] - v + bsum[blockIdx.x];
    if (i < NN) { csr_start[i] = excl; cursor[i] = excl; }
    if (i == NN - 1) csr_start[NN] = excl + v;
}

__global__ void k_fill_csr(const int* __restrict__ src, const int* __restrict__ dst,
                           int* __restrict__ cursor, int* __restrict__ csr_src) {
    int e = blockIdx.x * blockDim.x + threadIdx.x;
    if (e >= EE) return;
    int pos = atomicAdd(&cursor[dst[e]], 1);
    csr_src[pos] = src[e];
}

// ---------------------------------------------------------------------------
// FFMA GEMM: hs[N,128] = f(X)[N,K] @ W[K,128], output fp16 (NO cs scaling —
// cs is folded into the gather).  If NORM: f(x) = leaky(x*alpha[c]+beta[c]),
// alpha/beta computed per block from the previous layer's stats.
// Block: 64 rows x 128 cols, 256 threads, 8x4 micro-tile, BK=32.
// ---------------------------------------------------------------------------
template <int K, bool NORM>
__global__ void __launch_bounds__(256, 2)
k_gemm(const float* __restrict__ X, const float* __restrict__ W,
       const float* __restrict__ stats, const float* __restrict__ gw,
       const float* __restrict__ gb, const float* __restrict__ gs,
       __half* __restrict__ out) {
    constexpr int BK = 32;
    __shared__ float Ws[BK][HID];
    __shared__ float Xs[64][BK];
    __shared__ float s_a[HID], s_b[HID];

    int tid = threadIdx.x;
    int tx = tid & 31, ty = tid >> 5;
    int row0 = blockIdx.x * 64;
    int rb = ty * 8, cb = tx * 4;

    if (NORM) {
        if (tid < HID) {
            float a, b;
            alpha_beta(stats, gw, gb, gs, tid, a, b);
            s_a[tid] = a;
            s_b[tid] = b;
        }
        __syncthreads();
    }

    float acc[8][4];
#pragma unroll
    for (int i = 0; i < 8; i++)
#pragma unroll
        for (int j = 0; j < 4; j++) acc[i][j] = 0.f;

    for (int k0 = 0; k0 < K; k0 += BK) {
        for (int i = tid; i < BK * 32; i += 256) {
            int k = i >> 5, c = (i & 31) * 4;
            *(float4*)&Ws[k][c] = *(const float4*)&W[(k0 + k) * HID + c];
        }
        for (int i = tid; i < 64 * (BK / 4); i += 256) {
            int r = i / (BK / 4), k4 = (i % (BK / 4)) * 4;
            int g = row0 + r;
            float4 v = make_float4(0.f, 0.f, 0.f, 0.f);
            if (g < NN) v = *(const float4*)&X[(size_t)g * K + k0 + k4];
            if (NORM) {
                float4 a = *(const float4*)&s_a[k0 + k4];
                float4 b = *(const float4*)&s_b[k0 + k4];
                v.x = leaky(v.x * a.x + b.x);
                v.y = leaky(v.y * a.y + b.y);
                v.z = leaky(v.z * a.z + b.z);
                v.w = leaky(v.w * a.w + b.w);
            }
            *(float4*)&Xs[r][k4] = v;
        }
        __syncthreads();

#pragma unroll
        for (int k = 0; k < BK; k += 4) {
            float xv[8][4];
#pragma unroll
            for (int i = 0; i < 8; i++)
                *(float4*)xv[i] = *(const float4*)&Xs[rb + i][k];
#pragma unroll
            for (int kk = 0; kk < 4; kk++) {
                float4 w = *(const float4*)&Ws[k + kk][cb];
#pragma unroll
                for (int i = 0; i < 8; i++) {
                    float x = xv[i][kk];
                    acc[i][0] += x * w.x;
                    acc[i][1] += x * w.y;
                    acc[i][2] += x * w.z;
                    acc[i][3] += x * w.w;
                }
            }
        }
        __syncthreads();
    }

#pragma unroll
    for (int i = 0; i < 8; i++) {
        int g = row0 + rb + i;
        if (g < NN) {
            __half2 p0 = __floats2half2_rn(acc[i][0], acc[i][1]);
            __half2 p1 = __floats2half2_rn(acc[i][2], acc[i][3]);
            uint2 u;
            u.x = *reinterpret_cast<uint32_t*>(&p0);
            u.y = *reinterpret_cast<uint32_t*>(&p1);
            *(uint2*)&out[(size_t)g * HID + cb] = u;
        }
    }
}

// ---------------------------------------------------------------------------
// Fused aggregation (fp16 source): warp per dst node.
//   acc += hs[src] * cs[src]  (cs folded in; FMA instead of ADD)
//   y = acc * cd[dst] ; column sum/sumsq stats.
// 16 lanes per row (uint4 = 8 halves each); 2 half-lane groups x 2-deep
// unroll = 4 edges in flight per warp; shfl_xor(16) combine.
// ---------------------------------------------------------------------------
__global__ void __launch_bounds__(256)
k_aggstats(const __half* __restrict__ hs, const int* __restrict__ csr_start,
           const int* __restrict__ csr_src, const float* __restrict__ cs,
           const float* __restrict__ cd,
           float* __restrict__ y, float* __restrict__ stats) {
    __shared__ float s_sum[8][HID];
    __shared__ float s_sq [8][HID];

    int warp = threadIdx.x >> 5, lane = threadIdx.x & 31;
    int lg = lane >> 4, li = lane & 15;
    int d = blockIdx.x * 8 + warp;

    float2 acc[4];
#pragma unroll
    for (int j = 0; j < 4; j++) acc[j] = make_float2(0.f, 0.f);

    if (d < NN) {
        int start = __ldg(&csr_start[d]);
        int end   = __ldg(&csr_start[d + 1]);
        for (int i = start; i < end; i += 4) {
            int e0 = i + lg;
            int e1 = i + lg + 2;
            if (e0 < end) {
                int s = __ldg(&csr_src[e0]);
                float w = __ldg(&cs[s]);
                uint4 u = __ldg((const uint4*)(hs + (size_t)s * HID) + li);
                float2 f;
                f = __half22float2(*reinterpret_cast<__half2*>(&u.x));
                acc[0].x = fmaf(f.x, w, acc[0].x); acc[0].y = fmaf(f.y, w, acc[0].y);
                f = __half22float2(*reinterpret_cast<__half2*>(&u.y));
                acc[1].x = fmaf(f.x, w, acc[1].x); acc[1].y = fmaf(f.y, w, acc[1].y);
                f = __half22float2(*reinterpret_cast<__half2*>(&u.z));
                acc[2].x = fmaf(f.x, w, acc[2].x); acc[2].y = fmaf(f.y, w, acc[2].y);
                f = __half22float2(*reinterpret_cast<__half2*>(&u.w));
                acc[3].x = fmaf(f.x, w, acc[3].x); acc[3].y = fmaf(f.y, w, acc[3].y);
            }
            if (e1 < end) {
                int s = __ldg(&csr_src[e1]);
                float w = __ldg(&cs[s]);
                uint4 u = __ldg((const uint4*)(hs + (size_t)s * HID) + li);
                float2 f;
                f = __half22float2(*reinterpret_cast<__half2*>(&u.x));
                acc[0].x = fmaf(f.x, w, acc[0].x); acc[0].y = fmaf(f.y, w, acc[0].y);
                f = __half22float2(*reinterpret_cast<__half2*>(&u.y));
                acc[1].x = fmaf(f.x, w, acc[1].x); acc[1].y = fmaf(f.y, w, acc[1].y);
                f = __half22float2(*reinterpret_cast<__half2*>(&u.z));
                acc[2].x = fmaf(f.x, w, acc[2].x); acc[2].y = fmaf(f.y, w, acc[2].y);
                f = __half22float2(*reinterpret_cast<__half2*>(&u.w));
                acc[3].x = fmaf(f.x, w, acc[3].x); acc[3].y = fmaf(f.y, w, acc[3].y);
            }
        }
#pragma unroll
        for (int j = 0; j < 4; j++) {
            acc[j].x += __shfl_xor_sync(0xffffffffu, acc[j].x, 16);
            acc[j].y += __shfl_xor_sync(0xffffffffu, acc[j].y, 16);
        }
        float c = __ldg(&cd[d]);
#pragma unroll
        for (int j = 0; j < 4; j++) { acc[j].x *= c; acc[j].y *= c; }
        if (lg == 0) {
            float4 o0 = make_float4(acc[0].x, acc[0].y, acc[1].x, acc[1].y);
            float4 o1 = make_float4(acc[2].x, acc[2].y, acc[3].x, acc[3].y);
            *(float4*)(y + (size_t)d * HID + li * 8)     = o0;
            *(float4*)(y + (size_t)d * HID + li * 8 + 4) = o1;
        }
    }

    if (lg == 0) {
#pragma unroll
        for (int j = 0; j < 4; j++) {
            int c0 = li * 8 + 2 * j;
            float vx = (d < NN) ? acc[j].x : 0.f;
            float vy = (d < NN) ? acc[j].y : 0.f;
            s_sum[warp][c0]     = vx;
            s_sum[warp][c0 + 1] = vy;
            s_sq [warp][c0]     = vx * vx;
            s_sq [warp][c0 + 1] = vy * vy;
        }
    }
    __syncthreads();

    int t = threadIdx.x;
    if (t < HID) {
        float s = 0.f;
#pragma unroll
        for (int w = 0; w < 8; w++) s += s_sum[w][t];
        atomicAdd(&stats[t], s);
    } else {
        int c = t - HID;
        float s = 0.f;
#pragma unroll
        for (int w = 0; w < 8; w++) s += s_sq[w][c];
        atomicAdd(&stats[HID + c], s);
    }
}

// ---------------------------------------------------------------------------
// Readout: block per graph, thread per channel; alpha/beta per thread,
// norm+leaky on the fly.
// ---------------------------------------------------------------------------
__global__ void k_readout(const float* __restrict__ y,
                          const float* __restrict__ stats,
                          const float* __restrict__ gw, const float* __restrict__ gb,
                          const float* __restrict__ gs,
                          const int* __restrict__ gstart,
                          float* __restrict__ out, int layer) {
    int g = blockIdx.x;
    int c = threadIdx.x;
    float a, b;
    alpha_beta(stats, gw, gb, gs, c, a, b);
    int s0 = gstart[g], s1 = gstart[g + 1];
    float sum = 0.f, mx = -CUDART_INF_F, mn = CUDART_INF_F;
    for (int r = s0; r < s1; r++) {
        float v = leaky(__ldg(&y[(size_t)r * HID + c]) * a + b);
        sum += v;
        mx = fmaxf(mx, v);
        mn = fminf(mn, v);
    }
    int cnt = s1 - s0;
    float mean = sum / fmaxf((float)cnt, 1.f);
    if (cnt == 0) { mx = 0.f; mn = 0.f; }
    float* o = out + (size_t)g * (9 * HID) + layer * (3 * HID);
    o[c]           = leaky(mean);
    o[HID + c]     = leaky(mx);
    o[2 * HID + c] = leaky(mn);
}

// ---------------------------------------------------------------------------
// Launch: forked two-stream schedule (capture-safe via event fork/join).
//  stream0 (legacy): gemm0 | agg0 gemm1 agg1 gemm2 agg2 readout2
//  stream1:          setup chain        | readout0 | readout1
// y triple-buffered so readouts never race an agg write.
// ---------------------------------------------------------------------------
extern "C" void kernel_launch(void* const* d_in, const int* in_sizes, int n_in,
                              void* d_out, int out_size) {
    const float* X   = (const float*)d_in[0];
    const float* W1  = (const float*)d_in[1];
    const float* W2  = (const float*)d_in[2];
    const float* W3  = (const float*)d_in[3];
    const float* gw  = (const float*)d_in[4];
    const float* gb  = (const float*)d_in[5];
    const float* gs  = (const float*)d_in[6];
    const int*   src = (const int*)d_in[7];
    const int*   dst = (const int*)d_in[8];
    const int*   gid = (const int*)d_in[9];
    float* out = (float*)d_out;

    __half* hs;
    float *ya, *yb, *yc, *cs, *cd, *stats;
    int *deg, *gstart, *csr_start, *cursor, *csr_src, *bsum;
    cudaGetSymbolAddress((void**)&hs,        g_hs);
    cudaGetSymbolAddress((void**)&ya,        g_ya);
    cudaGetSymbolAddress((void**)&yb,        g_yb);
    cudaGetSymbolAddress((void**)&yc,        g_yc);
    cudaGetSymbolAddress((void**)&cs,        g_cs);
    cudaGetSymbolAddress((void**)&cd,        g_cd);
    cudaGetSymbolAddress((void**)&stats,     g_stats);
    cudaGetSymbolAddress((void**)&deg,       g_deg);
    cudaGetSymbolAddress((void**)&gstart,    g_gstart);
    cudaGetSymbolAddress((void**)&csr_start, g_csr_start);
    cudaGetSymbolAddress((void**)&cursor,    g_cursor);
    cudaGetSymbolAddress((void**)&csr_src,   g_csr_src);
    cudaGetSymbolAddress((void**)&bsum,      g_bsum);

    cudaStream_t s1;
    cudaStreamCreateWithFlags(&s1, cudaStreamNonBlocking);
    cudaEvent_t eF, eS, eA0, eA1, eR;
    cudaEventCreateWithFlags(&eF,  cudaEventDisableTiming);
    cudaEventCreateWithFlags(&eS,  cudaEventDisableTiming);
    cudaEventCreateWithFlags(&eA0, cudaEventDisableTiming);
    cudaEventCreateWithFlags(&eA1, cudaEventDisableTiming);
    cudaEventCreateWithFlags(&eR,  cudaEventDisableTiming);

    const int gemm_grid = (NN + 63) / 64;
    const int agg_grid  = (NN + 7) / 8;

    // fork
    cudaEventRecord(eF, 0);
    cudaStreamWaitEvent(s1, eF, 0);

    // stream0: GEMM0 (independent of graph structure now)
    k_gemm<INF_, false><<<gemm_grid, 256>>>(
        X, W1, nullptr, nullptr, nullptr, nullptr, hs);

    // stream1: full setup chain
    k_setup_zero<<<256, 256, 0, s1>>>(deg, stats);
    k_degrees<<<(EE + 255) / 256, 256, 0, s1>>>(src, dst, deg);
    k_invdeg<<<(NN + 255) / 256, 256, 0, s1>>>(deg, cs, cd);
    k_gstart<<<(NN + 255) / 256, 256, 0, s1>>>(gid, gstart);
    k_scan1<<<NB_SCAN, 256, 0, s1>>>(deg + NN, bsum);
    k_scan2<<<1, 256, 0, s1>>>(bsum);
    k_scan3<<<NB_SCAN, 256, 0, s1>>>(deg + NN, bsum, csr_start, cursor);
    k_fill_csr<<<(EE + 255) / 256, 256, 0, s1>>>(src, dst, cursor, csr_src);
    cudaEventRecord(eS, s1);
    cudaStreamWaitEvent(0, eS, 0);

    // layer 0
    k_aggstats<<<agg_grid, 256>>>(hs, csr_start, csr_src, cs, cd, ya, stats);
    cudaEventRecord(eA0, 0);

    // layer 1 gemm on stream0, readout0 concurrently on stream1
    k_gemm<HID, true><<<gemm_grid, 256>>>(ya, W2, stats, gw, gb, gs, hs);
    cudaStreamWaitEvent(s1, eA0, 0);
    k_readout<<<GG, HID, 0, s1>>>(ya, stats, gw, gb, gs, gstart, out, 0);

    k_aggstats<<<agg_grid, 256>>>(hs, csr_start, csr_src, cs, cd, yb,
                                  stats + 2 * HID);
    cudaEventRecord(eA1, 0);

    // layer 2 gemm on stream0, readout1 concurrently on stream1
    k_gemm<HID, true><<<gemm_grid, 256>>>(yb, W3, stats + 2 * HID,
                                          gw + HID, gb + HID, gs + HID, hs);
    cudaStreamWaitEvent(s1, eA1, 0);
    k_readout<<<GG, HID, 0, s1>>>(yb, stats + 2 * HID, gw + HID, gb + HID,
                                  gs + HID, gstart, out, 1);

    k_aggstats<<<agg_grid, 256>>>(hs, csr_start, csr_src, cs, cd, yc,
                                  stats + 4 * HID);
    k_readout<<<GG, HID>>>(yc, stats + 4 * HID, gw + 2 * HID, gb + 2 * HID,
                           gs + 2 * HID, gstart, out, 2);

    // join
    cudaEventRecord(eR, s1);
    cudaStreamWaitEvent(0, eR, 0);
}

// round 8
// speedup vs baseline: 1.0525x; 1.0525x over previous
#include <cuda_runtime.h>
#include <cuda_fp16.h>
#include <math_constants.h>
#include <cstdint>

// Problem constants (fixed by the dataset)
#define NN   50000
#define EE   600000
#define GG   1000
#define HID  128
#define INF_ 64
#define EPS  1e-5f
#define SLOPE 0.01f

#define NB_SCAN ((NN + 255) / 256)

// ---------------------------------------------------------------------------
// Scratch (static __device__ arrays; no allocation anywhere)
// ---------------------------------------------------------------------------
__device__ __half g_hs [NN * HID];    // x@W in fp16 (no cs), gather source
__device__ float  g_y  [NN * HID];    // y = agg * cd (pre-norm layer output)
__device__ float  g_cs [NN];
__device__ float  g_cd [NN];
__device__ int    g_deg[2 * NN];
__device__ int    g_csr_start[NN + 1];
__device__ int    g_cursor[NN];
__device__ int    g_csr_src[EE];
__device__ int    g_bsum[256];
__device__ float  g_stats[3 * 2 * HID];
__device__ int    g_gstart[GG + 1];

__device__ __forceinline__ float leaky(float v) { return v > 0.f ? v : SLOPE * v; }

// alpha/beta for channel c from this layer's stats + gn params
__device__ __forceinline__ void alpha_beta(const float* __restrict__ stats,
                                           const float* __restrict__ gw,
                                           const float* __restrict__ gb,
                                           const float* __restrict__ gs,
                                           int c, float& a, float& b) {
    float m   = stats[c] * (1.f / (float)NN);
    float ex2 = stats[HID + c] * (1.f / (float)NN);
    float s   = gs[c];
    float var = ex2 - m * m * (2.f * s - s * s);
    float inv = rsqrtf(var + EPS);
    a = inv * gw[c];
    b = gb[c] - s * m * a;
}

// packed f32x2 helpers
__device__ __forceinline__ unsigned long long pack2(float x, float y) {
    unsigned long long r;
    asm("mov.b64 %0, {%1, %2};" : "=l"(r) : "f"(x), "f"(y));
    return r;
}
__device__ __forceinline__ void unpack2(unsigned long long p, float& x, float& y) {
    asm("mov.b64 {%0, %1}, %2;" : "=f"(x), "=f"(y) : "l"(p));
}
__device__ __forceinline__ void fma2(unsigned long long& d, unsigned long long a,
                                     unsigned long long b) {
    asm("fma.rn.f32x2 %0, %1, %2, %0;" : "+l"(d) : "l"(a), "l"(b));
}

// ---------------------------------------------------------------------------
// Setup zero: deg + stats
// ---------------------------------------------------------------------------
__global__ void k_setup_zero(int* __restrict__ deg, float* __restrict__ stats) {
    int i = blockIdx.x * blockDim.x + threadIdx.x;
    int stride = gridDim.x * blockDim.x;
    for (int j = i; j < 2 * NN; j += stride) deg[j] = 0;
    for (int j = i; j < 3 * 2 * HID; j += stride) stats[j] = 0.f;
}

// ---------------------------------------------------------------------------
// Degrees
// ---------------------------------------------------------------------------
__global__ void k_degrees(const int* __restrict__ src, const int* __restrict__ dst,
                          int* __restrict__ deg) {
    int e = blockIdx.x * blockDim.x + threadIdx.x;
    if (e >= EE) return;
    atomicAdd(&deg[src[e]], 1);
    atomicAdd(&deg[NN + dst[e]], 1);
}

__global__ void k_invdeg(const int* __restrict__ deg,
                         float* __restrict__ cs, float* __restrict__ cd) {
    int i = blockIdx.x * blockDim.x + threadIdx.x;
    if (i >= NN) return;
    cs[i] = rsqrtf(fmaxf((float)deg[i], 1.f));
    cd[i] = rsqrtf(fmaxf((float)deg[NN + i], 1.f));
}

// ---------------------------------------------------------------------------
// Graph segment starts (graph_ids sorted ascending)
// ---------------------------------------------------------------------------
__global__ void k_gstart(const int* __restrict__ gid, int* __restrict__ gstart) {
    int i = blockIdx.x * blockDim.x + threadIdx.x;
    if (i >= NN) return;
    int g  = gid[i];
    int gp = (i == 0) ? -1 : gid[i - 1];
    for (int gg = gp + 1; gg <= g; gg++) gstart[gg] = i;
    if (i == NN - 1)
        for (int gg = g + 1; gg <= GG; gg++) gstart[gg] = NN;
}

// ---------------------------------------------------------------------------
// CSR-by-dst build (3-step scan + fill)
// ---------------------------------------------------------------------------
__global__ void k_scan1(const int* __restrict__ indeg, int* __restrict__ bsum) {
    __shared__ int sh[256];
    int i = blockIdx.x * 256 + threadIdx.x;
    sh[threadIdx.x] = (i < NN) ? indeg[i] : 0;
    __syncthreads();
    for (int o = 128; o > 0; o >>= 1) {
        if (threadIdx.x < o) sh[threadIdx.x] += sh[threadIdx.x + o];
        __syncthreads();
    }
    if (threadIdx.x == 0) bsum[blockIdx.x] = sh[0];
}

__global__ void k_scan2(int* __restrict__ bsum) {
    __shared__ int sh[256];
    int tid = threadIdx.x;
    int v = (tid < NB_SCAN) ? bsum[tid] : 0;
    sh[tid] = v;
    __syncthreads();
    for (int o = 1; o < 256; o <<= 1) {
        int t = (tid >= o) ? sh[tid - o] : 0;
        __syncthreads();
        sh[tid] += t;
        __syncthreads();
    }
    if (tid < NB_SCAN) bsum[tid] = sh[tid] - v;
}

__global__ void k_scan3(const int* __restrict__ indeg, const int* __restrict__ bsum,
                        int* __restrict__ csr_start, int* __restrict__ cursor) {
    __shared__ int sh[256];
    int tid = threadIdx.x;
    int i = blockIdx.x * 256 + tid;
    int v = (i < NN) ? indeg[i] : 0;
    sh[tid] = v;
    __syncthreads();
    for (int o = 1; o < 256; o <<= 1) {
        int t = (tid >= o) ? sh[tid - o] : 0;
        __syncthreads();
        sh[tid] += t;
        __syncthreads();
    }
    int excl = sh[tid] - v + bsum[blockIdx.x];
    if (i < NN) { csr_start[i] = excl; cursor[i] = excl; }
    if (i == NN - 1) csr_start[NN] = excl + v;
}

__global__ void k_fill_csr(const int* __restrict__ src, const int* __restrict__ dst,
                           int* __restrict__ cursor, int* __restrict__ csr_src) {
    int e = blockIdx.x * blockDim.x + threadIdx.x;
    if (e >= EE) return;
    int pos = atomicAdd(&cursor[dst[e]], 1);
    csr_src[pos] = src[e];
}

// ---------------------------------------------------------------------------
// Packed-f32x2 GEMM: hs[N,128] = f(X)[N,K] @ W[K,128], output fp16.
// Block 64 rows x 128 cols, 256 threads, micro-tile 8 rows x 4 cols.
// X staged K-MAJOR in smem so row-pairs are packed 64-bit operands for
// fma.rn.f32x2 (2 full-precision fp32 FMAs per instruction). Only W needs
// broadcast packing (4 mov.b64 per k, amortized over 16 FFMA2).
// If NORM: f(x) = leaky(x*alpha[c]+beta[c]), alpha/beta from prev stats.
// ---------------------------------------------------------------------------
template <int K, bool NORM>
__global__ void __launch_bounds__(256, 2)
k_gemm(const float* __restrict__ X, const float* __restrict__ W,
       const float* __restrict__ stats, const float* __restrict__ gw,
       const float* __restrict__ gb, const float* __restrict__ gs,
       __half* __restrict__ out) {
    constexpr int BK = 32;
    __shared__ float Ws[BK][HID];
    __shared__ float Xs[BK][68];          // k-major, 68-pad (272B rows, 16B-aligned)
    __shared__ float s_a[HID], s_b[HID];

    int tid = threadIdx.x;
    int tx = tid & 31, ty = tid >> 5;
    int row0 = blockIdx.x * 64;
    int rb = ty * 8, cb = tx * 4;

    if (NORM) {
        if (tid < HID) {
            float a, b;
            alpha_beta(stats, gw, gb, gs, tid, a, b);
            s_a[tid] = a;
            s_b[tid] = b;
        }
        __syncthreads();
    }

    // acc[rowpair][col]: rowpair rp covers rows (rb+2rp, rb+2rp+1)
    unsigned long long acc[4][4];
#pragma unroll
    for (int i = 0; i < 4; i++)
#pragma unroll
        for (int j = 0; j < 4; j++) acc[i][j] = 0ull;

    for (int k0 = 0; k0 < K; k0 += BK) {
        // stage W chunk [BK][128]
        for (int i = tid; i < BK * 32; i += 256) {
            int k = i >> 5, c = (i & 31) * 4;
            *(float4*)&Ws[k][c] = *(const float4*)&W[(k0 + k) * HID + c];
        }
        // stage X chunk k-major: Xs[k][r] = f(X[row0+r][k0+k])
        for (int i = tid; i < 64 * 8; i += 256) {
            int r = i >> 3, kq = (i & 7) * 4;
            int g = row0 + r;
            float4 v = make_float4(0.f, 0.f, 0.f, 0.f);
            if (g < NN) v = *(const float4*)&X[(size_t)g * K + k0 + kq];
            if (NORM) {
                float4 a = *(const float4*)&s_a[k0 + kq];
                float4 b = *(const float4*)&s_b[k0 + kq];
                v.x = leaky(v.x * a.x + b.x);
                v.y = leaky(v.y * a.y + b.y);
                v.z = leaky(v.z * a.z + b.z);
                v.w = leaky(v.w * a.w + b.w);
            }
            Xs[kq + 0][r] = v.x;
            Xs[kq + 1][r] = v.y;
            Xs[kq + 2][r] = v.z;
            Xs[kq + 3][r] = v.w;
        }
        __syncthreads();

#pragma unroll
        for (int k = 0; k < BK; k++) {
            // 4 packed row-pairs (8 rows) via two 16B loads (warp-broadcast)
            ulonglong2 xa = *(const ulonglong2*)&Xs[k][rb];
            ulonglong2 xb = *(const ulonglong2*)&Xs[k][rb + 4];
            float4 w = *(const float4*)&Ws[k][cb];
            unsigned long long w0 = pack2(w.x, w.x);
            unsigned long long w1 = pack2(w.y, w.y);
            unsigned long long w2 = pack2(w.z, w.z);
            unsigned long long w3 = pack2(w.w, w.w);
            fma2(acc[0][0], xa.x, w0); fma2(acc[0][1], xa.x, w1);
            fma2(acc[0][2], xa.x, w2); fma2(acc[0][3], xa.x, w3);
            fma2(acc[1][0], xa.y, w0); fma2(acc[1][1], xa.y, w1);
            fma2(acc[1][2], xa.y, w2); fma2(acc[1][3], xa.y, w3);
            fma2(acc[2][0], xb.x, w0); fma2(acc[2][1], xb.x, w1);
            fma2(acc[2][2], xb.x, w2); fma2(acc[2][3], xb.x, w3);
            fma2(acc[3][0], xb.y, w0); fma2(acc[3][1], xb.y, w1);
            fma2(acc[3][2], xb.y, w2); fma2(acc[3][3], xb.y, w3);
        }
        __syncthreads();
    }

    // epilogue: unpack row-pairs, convert to fp16, store
#pragma unroll
    for (int rp = 0; rp < 4; rp++) {
        float lo[4], hi[4];
#pragma unroll
        for (int c = 0; c < 4; c++) unpack2(acc[rp][c], lo[c], hi[c]);
        int g0 = row0 + rb + 2 * rp;
        int g1 = g0 + 1;
        if (g0 < NN) {
            __half2 p0 = __floats2half2_rn(lo[0], lo[1]);
            __half2 p1 = __floats2half2_rn(lo[2], lo[3]);
            uint2 u;
            u.x = *reinterpret_cast<uint32_t*>(&p0);
            u.y = *reinterpret_cast<uint32_t*>(&p1);
            *(uint2*)&out[(size_t)g0 * HID + cb] = u;
        }
        if (g1 < NN) {
            __half2 p0 = __floats2half2_rn(hi[0], hi[1]);
            __half2 p1 = __floats2half2_rn(hi[2], hi[3]);
            uint2 u;
            u.x = *reinterpret_cast<uint32_t*>(&p0);
            u.y = *reinterpret_cast<uint32_t*>(&p1);
            *(uint2*)&out[(size_t)g1 * HID + cb] = u;
        }
    }
}

// ---------------------------------------------------------------------------
// Fused aggregation (fp16 source): warp per dst node.
//   acc += hs[src] * cs[src] ; y = acc * cd[dst] ; column stats.
// 16 lanes per 256B row; 2 half-lane groups x 2-deep unroll = 4 edges in
// flight; shfl_xor(16) combine.
// ---------------------------------------------------------------------------
__global__ void __launch_bounds__(256)
k_aggstats(const __half* __restrict__ hs, const int* __restrict__ csr_start,
           const int* __restrict__ csr_src, const float* __restrict__ cs,
           const float* __restrict__ cd,
           float* __restrict__ y, float* __restrict__ stats) {
    __shared__ float s_sum[8][HID];
    __shared__ float s_sq [8][HID];

    int warp = threadIdx.x >> 5, lane = threadIdx.x & 31;
    int lg = lane >> 4, li = lane & 15;
    int d = blockIdx.x * 8 + warp;

    float2 acc[4];
#pragma unroll
    for (int j = 0; j < 4; j++) acc[j] = make_float2(0.f, 0.f);

    if (d < NN) {
        int start = __ldg(&csr_start[d]);
        int end   = __ldg(&csr_start[d + 1]);
        for (int i = start; i < end; i += 4) {
            int e0 = i + lg;
            int e1 = i + lg + 2;
            if (e0 < end) {
                int s = __ldg(&csr_src[e0]);
                float w = __ldg(&cs[s]);
                uint4 u = __ldg((const uint4*)(hs + (size_t)s * HID) + li);
                float2 f;
                f = __half22float2(*reinterpret_cast<__half2*>(&u.x));
                acc[0].x = fmaf(f.x, w, acc[0].x); acc[0].y = fmaf(f.y, w, acc[0].y);
                f = __half22float2(*reinterpret_cast<__half2*>(&u.y));
                acc[1].x = fmaf(f.x, w, acc[1].x); acc[1].y = fmaf(f.y, w, acc[1].y);
                f = __half22float2(*reinterpret_cast<__half2*>(&u.z));
                acc[2].x = fmaf(f.x, w, acc[2].x); acc[2].y = fmaf(f.y, w, acc[2].y);
                f = __half22float2(*reinterpret_cast<__half2*>(&u.w));
                acc[3].x = fmaf(f.x, w, acc[3].x); acc[3].y = fmaf(f.y, w, acc[3].y);
            }
            if (e1 < end) {
                int s = __ldg(&csr_src[e1]);
                float w = __ldg(&cs[s]);
                uint4 u = __ldg((const uint4*)(hs + (size_t)s * HID) + li);
                float2 f;
                f = __half22float2(*reinterpret_cast<__half2*>(&u.x));
                acc[0].x = fmaf(f.x, w, acc[0].x); acc[0].y = fmaf(f.y, w, acc[0].y);
                f = __half22float2(*reinterpret_cast<__half2*>(&u.y));
                acc[1].x = fmaf(f.x, w, acc[1].x); acc[1].y = fmaf(f.y, w, acc[1].y);
                f = __half22float2(*reinterpret_cast<__half2*>(&u.z));
                acc[2].x = fmaf(f.x, w, acc[2].x); acc[2].y = fmaf(f.y, w, acc[2].y);
                f = __half22float2(*reinterpret_cast<__half2*>(&u.w));
                acc[3].x = fmaf(f.x, w, acc[3].x); acc[3].y = fmaf(f.y, w, acc[3].y);
            }
        }
#pragma unroll
        for (int j = 0; j < 4; j++) {
            acc[j].x += __shfl_xor_sync(0xffffffffu, acc[j].x, 16);
            acc[j].y += __shfl_xor_sync(0xffffffffu, acc[j].y, 16);
        }
        float c = __ldg(&cd[d]);
#pragma unroll
        for (int j = 0; j < 4; j++) { acc[j].x *= c; acc[j].y *= c; }
        if (lg == 0) {
            float4 o0 = make_float4(acc[0].x, acc[0].y, acc[1].x, acc[1].y);
            float4 o1 = make_float4(acc[2].x, acc[2].y, acc[3].x, acc[3].y);
            *(float4*)(y + (size_t)d * HID + li * 8)     = o0;
            *(float4*)(y + (size_t)d * HID + li * 8 + 4) = o1;
        }
    }

    if (lg == 0) {
#pragma unroll
        for (int j = 0; j < 4; j++) {
            int c0 = li * 8 + 2 * j;
            float vx = (d < NN) ? acc[j].x : 0.f;
            float vy = (d < NN) ? acc[j].y : 0.f;
            s_sum[warp][c0]     = vx;
            s_sum[warp][c0 + 1] = vy;
            s_sq [warp][c0]     = vx * vx;
            s_sq [warp][c0 + 1] = vy * vy;
        }
    }
    __syncthreads();

    int t = threadIdx.x;
    if (t < HID) {
        float s = 0.f;
#pragma unroll
        for (int w = 0; w < 8; w++) s += s_sum[w][t];
        atomicAdd(&stats[t], s);
    } else {
        int c = t - HID;
        float s = 0.f;
#pragma unroll
        for (int w = 0; w < 8; w++) s += s_sq[w][c];
        atomicAdd(&stats[HID + c], s);
    }
}

// ---------------------------------------------------------------------------
// Readout: block per graph, thread per channel; alpha/beta per thread,
// norm+leaky on the fly.
// ---------------------------------------------------------------------------
__global__ void k_readout(const float* __restrict__ y,
                          const float* __restrict__ stats,
                          const float* __restrict__ gw, const float* __restrict__ gb,
                          const float* __restrict__ gs,
                          const int* __restrict__ gstart,
                          float* __restrict__ out, int layer) {
    int g = blockIdx.x;
    int c = threadIdx.x;
    float a, b;
    alpha_beta(stats, gw, gb, gs, c, a, b);
    int s0 = gstart[g], s1 = gstart[g + 1];
    float sum = 0.f, mx = -CUDART_INF_F, mn = CUDART_INF_F;
    for (int r = s0; r < s1; r++) {
        float v = leaky(__ldg(&y[(size_t)r * HID + c]) * a + b);
        sum += v;
        mx = fmaxf(mx, v);
        mn = fminf(mn, v);
    }
    int cnt = s1 - s0;
    float mean = sum / fmaxf((float)cnt, 1.f);
    if (cnt == 0) { mx = 0.f; mn = 0.f; }
    float* o = out + (size_t)g * (9 * HID) + layer * (3 * HID);
    o[c]           = leaky(mean);
    o[HID + c]     = leaky(mx);
    o[2 * HID + c] = leaky(mn);
}

// ---------------------------------------------------------------------------
// Launch: single stream (round-6 two-stream overlap measured neutral/negative)
// ---------------------------------------------------------------------------
extern "C" void kernel_launch(void* const* d_in, const int* in_sizes, int n_in,
                              void* d_out, int out_size) {
    const float* X   = (const float*)d_in[0];
    const float* W1  = (const float*)d_in[1];
    const float* W2  = (const float*)d_in[2];
    const float* W3  = (const float*)d_in[3];
    const float* gw  = (const float*)d_in[4];
    const float* gb  = (const float*)d_in[5];
    const float* gs  = (const float*)d_in[6];
    const int*   src = (const int*)d_in[7];
    const int*   dst = (const int*)d_in[8];
    const int*   gid = (const int*)d_in[9];
    float* out = (float*)d_out;

    __half* hs;
    float *y, *cs, *cd, *stats;
    int *deg, *gstart, *csr_start, *cursor, *csr_src, *bsum;
    cudaGetSymbolAddress((void**)&hs,        g_hs);
    cudaGetSymbolAddress((void**)&y,         g_y);
    cudaGetSymbolAddress((void**)&cs,        g_cs);
    cudaGetSymbolAddress((void**)&cd,        g_cd);
    cudaGetSymbolAddress((void**)&stats,     g_stats);
    cudaGetSymbolAddress((void**)&deg,       g_deg);
    cudaGetSymbolAddress((void**)&gstart,    g_gstart);
    cudaGetSymbolAddress((void**)&csr_start, g_csr_start);
    cudaGetSymbolAddress((void**)&cursor,    g_cursor);
    cudaGetSymbolAddress((void**)&csr_src,   g_csr_src);
    cudaGetSymbolAddress((void**)&bsum,      g_bsum);

    // --- setup: degrees, segment starts, dst-CSR ---
    k_setup_zero<<<256, 256>>>(deg, stats);
    k_degrees<<<(EE + 255) / 256, 256>>>(src, dst, deg);
    k_invdeg<<<(NN + 255) / 256, 256>>>(deg, cs, cd);
    k_gstart<<<(NN + 255) / 256, 256>>>(gid, gstart);
    k_scan1<<<NB_SCAN, 256>>>(deg + NN, bsum);
    k_scan2<<<1, 256>>>(bsum);
    k_scan3<<<NB_SCAN, 256>>>(deg + NN, bsum, csr_start, cursor);
    k_fill_csr<<<(EE + 255) / 256, 256>>>(src, dst, cursor, csr_src);

    const float* Wl[3] = {W1, W2, W3};
    const int gemm_grid = (NN + 63) / 64;
    const int agg_grid  = (NN + 7) / 8;

    for (int L = 0; L < 3; L++) {
        if (L == 0)
            k_gemm<INF_, false><<<gemm_grid, 256>>>(
                X, Wl[0], nullptr, nullptr, nullptr, nullptr, hs);
        else
            k_gemm<HID, true><<<gemm_grid, 256>>>(
                y, Wl[L], stats + (L - 1) * 2 * HID,
                gw + (L - 1) * HID, gb + (L - 1) * HID, gs + (L - 1) * HID, hs);

        k_aggstats<<<agg_grid, 256>>>(hs, csr_start, csr_src, cs, cd, y,
                                      stats + L * 2 * HID);

        k_readout<<<GG, HID>>>(y, stats + L * 2 * HID, gw + L * HID,
                               gb + L * HID, gs + L * HID, gstart, out, L);
    }
}

// round 10
// speedup vs baseline: 1.0597x; 1.0069x over previous
#include <cuda_runtime.h>
#include <cuda_fp16.h>
#include <math_constants.h>
#include <cstdint>

// Problem constants (fixed by the dataset)
#define NN   50000
#define EE   600000
#define GG   1000
#define HID  128
#define INF_ 64
#define EPS  1e-5f
#define SLOPE 0.01f

#define NB_SCAN ((NN + 255) / 256)   // 196

// ---------------------------------------------------------------------------
// Scratch (static __device__ arrays; no allocation anywhere)
// ---------------------------------------------------------------------------
__device__ __half g_hs [NN * HID];    // x@W in fp16 (no cs), gather source
__device__ float  g_y  [NN * HID];    // y = agg * cd (pre-norm layer output)
__device__ float  g_cs [NN];
__device__ float  g_cd [NN];
__device__ int    g_deg[2 * NN];
__device__ int    g_csr_start[NN + 1];
__device__ int    g_cursor[NN];
__device__ int    g_csr_src[EE];
__device__ int    g_bsum[256];
__device__ float  g_stats[3 * 2 * HID];
__device__ int    g_gstart[GG + 1];

__device__ __forceinline__ float leaky(float v) { return v > 0.f ? v : SLOPE * v; }

__device__ __forceinline__ void alpha_beta(const float* __restrict__ stats,
                                           const float* __restrict__ gw,
                                           const float* __restrict__ gb,
                                           const float* __restrict__ gs,
                                           int c, float& a, float& b) {
    float m   = stats[c] * (1.f / (float)NN);
    float ex2 = stats[HID + c] * (1.f / (float)NN);
    float s   = gs[c];
    float var = ex2 - m * m * (2.f * s - s * s);
    float inv = rsqrtf(var + EPS);
    a = inv * gw[c];
    b = gb[c] - s * m * a;
}

// packed f32x2 helpers
__device__ __forceinline__ unsigned long long pack2(float x, float y) {
    unsigned long long r;
    asm("mov.b64 %0, {%1, %2};" : "=l"(r) : "f"(x), "f"(y));
    return r;
}
__device__ __forceinline__ void unpack2(unsigned long long p, float& x, float& y) {
    asm("mov.b64 {%0, %1}, %2;" : "=f"(x), "=f"(y) : "l"(p));
}
__device__ __forceinline__ void fma2(unsigned long long& d, unsigned long long a,
                                     unsigned long long b) {
    asm("fma.rn.f32x2 %0, %1, %2, %0;" : "+l"(d) : "l"(a), "l"(b));
}

// ---------------------------------------------------------------------------
// Setup zero: deg + stats
// ---------------------------------------------------------------------------
__global__ void k_setup_zero(int* __restrict__ deg, float* __restrict__ stats) {
    int i = blockIdx.x * blockDim.x + threadIdx.x;
    int stride = gridDim.x * blockDim.x;
    for (int j = i; j < 2 * NN; j += stride) deg[j] = 0;
    for (int j = i; j < 3 * 2 * HID; j += stride) stats[j] = 0.f;
}

// ---------------------------------------------------------------------------
// Degrees
// ---------------------------------------------------------------------------
__global__ void k_degrees(const int* __restrict__ src, const int* __restrict__ dst,
                          int* __restrict__ deg) {
    int e = blockIdx.x * blockDim.x + threadIdx.x;
    if (e >= EE) return;
    atomicAdd(&deg[src[e]], 1);
    atomicAdd(&deg[NN + dst[e]], 1);
}

// ---------------------------------------------------------------------------
// Fused post-degree setup: invdeg + graph segment starts + scan1 block sums.
// All inputs depend only on completed k_degrees; grid = NB_SCAN x 256.
// ---------------------------------------------------------------------------
__global__ void k_misc(const int* __restrict__ deg, const int* __restrict__ gid,
                       float* __restrict__ cs, float* __restrict__ cd,
                       int* __restrict__ gstart, int* __restrict__ bsum) {
    __shared__ int sh[256];
    int t = threadIdx.x;
    int i = blockIdx.x * 256 + t;
    int v = 0;
    if (i < NN) {
        int od = deg[i], id = deg[NN + i];
        cs[i] = rsqrtf(fmaxf((float)od, 1.f));
        cd[i] = rsqrtf(fmaxf((float)id, 1.f));
        v = id;
        int g  = gid[i];
        int gp = (i == 0) ? -1 : gid[i - 1];
        for (int gg = gp + 1; gg <= g; gg++) gstart[gg] = i;
        if (i == NN - 1)
            for (int gg = g + 1; gg <= GG; gg++) gstart[gg] = NN;
    }
    sh[t] = v;
    __syncthreads();
    for (int o = 128; o > 0; o >>= 1) {
        if (t < o) sh[t] += sh[t + o];
        __syncthreads();
    }
    if (t == 0) bsum[blockIdx.x] = sh[0];
}

__global__ void k_scan2(int* __restrict__ bsum) {
    __shared__ int sh[256];
    int tid = threadIdx.x;
    int v = (tid < NB_SCAN) ? bsum[tid] : 0;
    sh[tid] = v;
    __syncthreads();
    for (int o = 1; o < 256; o <<= 1) {
        int t = (tid >= o) ? sh[tid - o] : 0;
        __syncthreads();
        sh[tid] += t;
        __syncthreads();
    }
    if (tid < NB_SCAN) bsum[tid] = sh[tid] - v;
}

__global__ void k_scan3(const int* __restrict__ indeg, const int* __restrict__ bsum,
                        int* __restrict__ csr_start, int* __restrict__ cursor) {
    __shared__ int sh[256];
    int tid = threadIdx.x;
    int i = blockIdx.x * 256 + tid;
    int v = (i < NN) ? indeg[i] : 0;
    sh[tid] = v;
    __syncthreads();
    for (int o = 1; o < 256; o <<= 1) {
        int t = (tid >= o) ? sh[tid - o] : 0;
        __syncthreads();
        sh[tid] += t;
        __syncthreads();
    }
    int excl = sh[tid] - v + bsum[blockIdx.x];
    if (i < NN) { csr_start[i] = excl; cursor[i] = excl; }
    if (i == NN - 1) csr_start[NN] = excl + v;
}

__global__ void k_fill_csr(const int* __restrict__ src, const int* __restrict__ dst,
                           int* __restrict__ cursor, int* __restrict__ csr_src) {
    int e = blockIdx.x * blockDim.x + threadIdx.x;
    if (e >= EE) return;
    int pos = atomicAdd(&cursor[dst[e]], 1);
    csr_src[pos] = src[e];
}

// ---------------------------------------------------------------------------
// Packed-f32x2 GEMM: hs[N,128] = f(X)[N,K] @ W[K,128], output fp16.
// (round-8 proven)
// ---------------------------------------------------------------------------
template <int K, bool NORM>
__global__ void __launch_bounds__(256, 2)
k_gemm(const float* __restrict__ X, const float* __restrict__ W,
       const float* __restrict__ stats, const float* __restrict__ gw,
       const float* __restrict__ gb, const float* __restrict__ gs,
       __half* __restrict__ out) {
    constexpr int BK = 32;
    __shared__ float Ws[BK][HID];
    __shared__ float Xs[BK][68];
    __shared__ float s_a[HID], s_b[HID];

    int tid = threadIdx.x;
    int tx = tid & 31, ty = tid >> 5;
    int row0 = blockIdx.x * 64;
    int rb = ty * 8, cb = tx * 4;

    if (NORM) {
        if (tid < HID) {
            float a, b;
            alpha_beta(stats, gw, gb, gs, tid, a, b);
            s_a[tid] = a;
            s_b[tid] = b;
        }
        __syncthreads();
    }

    unsigned long long acc[4][4];
#pragma unroll
    for (int i = 0; i < 4; i++)
#pragma unroll
        for (int j = 0; j < 4; j++) acc[i][j] = 0ull;

    for (int k0 = 0; k0 < K; k0 += BK) {
        for (int i = tid; i < BK * 32; i += 256) {
            int k = i >> 5, c = (i & 31) * 4;
            *(float4*)&Ws[k][c] = *(const float4*)&W[(k0 + k) * HID + c];
        }
        for (int i = tid; i < 64 * 8; i += 256) {
            int r = i >> 3, kq = (i & 7) * 4;
            int g = row0 + r;
            float4 v = make_float4(0.f, 0.f, 0.f, 0.f);
            if (g < NN) v = *(const float4*)&X[(size_t)g * K + k0 + kq];
            if (NORM) {
                float4 a = *(const float4*)&s_a[k0 + kq];
                float4 b = *(const float4*)&s_b[k0 + kq];
                v.x = leaky(v.x * a.x + b.x);
                v.y = leaky(v.y * a.y + b.y);
                v.z = leaky(v.z * a.z + b.z);
                v.w = leaky(v.w * a.w + b.w);
            }
            Xs[kq + 0][r] = v.x;
            Xs[kq + 1][r] = v.y;
            Xs[kq + 2][r] = v.z;
            Xs[kq + 3][r] = v.w;
        }
        __syncthreads();

#pragma unroll
        for (int k = 0; k < BK; k++) {
            ulonglong2 xa = *(const ulonglong2*)&Xs[k][rb];
            ulonglong2 xb = *(const ulonglong2*)&Xs[k][rb + 4];
            float4 w = *(const float4*)&Ws[k][cb];
            unsigned long long w0 = pack2(w.x, w.x);
            unsigned long long w1 = pack2(w.y, w.y);
            unsigned long long w2 = pack2(w.z, w.z);
            unsigned long long w3 = pack2(w.w, w.w);
            fma2(acc[0][0], xa.x, w0); fma2(acc[0][1], xa.x, w1);
            fma2(acc[0][2], xa.x, w2); fma2(acc[0][3], xa.x, w3);
            fma2(acc[1][0], xa.y, w0); fma2(acc[1][1], xa.y, w1);
            fma2(acc[1][2], xa.y, w2); fma2(acc[1][3], xa.y, w3);
            fma2(acc[2][0], xb.x, w0); fma2(acc[2][1], xb.x, w1);
            fma2(acc[2][2], xb.x, w2); fma2(acc[2][3], xb.x, w3);
            fma2(acc[3][0], xb.y, w0); fma2(acc[3][1], xb.y, w1);
            fma2(acc[3][2], xb.y, w2); fma2(acc[3][3], xb.y, w3);
        }
        __syncthreads();
    }

#pragma unroll
    for (int rp = 0; rp < 4; rp++) {
        float lo[4], hi[4];
#pragma unroll
        for (int c = 0; c < 4; c++) unpack2(acc[rp][c], lo[c], hi[c]);
        int g0 = row0 + rb + 2 * rp;
        int g1 = g0 + 1;
        if (g0 < NN) {
            __half2 p0 = __floats2half2_rn(lo[0], lo[1]);
            __half2 p1 = __floats2half2_rn(lo[2], lo[3]);
            uint2 u;
            u.x = *reinterpret_cast<uint32_t*>(&p0);
            u.y = *reinterpret_cast<uint32_t*>(&p1);
            *(uint2*)&out[(size_t)g0 * HID + cb] = u;
        }
        if (g1 < NN) {
            __half2 p0 = __floats2half2_rn(hi[0], hi[1]);
            __half2 p1 = __floats2half2_rn(hi[2], hi[3]);
            uint2 u;
            u.x = *reinterpret_cast<uint32_t*>(&p0);
            u.y = *reinterpret_cast<uint32_t*>(&p1);
            *(uint2*)&out[(size_t)g1 * HID + cb] = u;
        }
    }
}

// ---------------------------------------------------------------------------
// Fused aggregation (fp16 source): warp per dst node. (round-8 proven)
// ---------------------------------------------------------------------------
__global__ void __launch_bounds__(256)
k_aggstats(const __half* __restrict__ hs, const int* __restrict__ csr_start,
           const int* __restrict__ csr_src, const float* __restrict__ cs,
           const float* __restrict__ cd,
           float* __restrict__ y, float* __restrict__ stats) {
    __shared__ float s_sum[8][HID];
    __shared__ float s_sq [8][HID];

    int warp = threadIdx.x >> 5, lane = threadIdx.x & 31;
    int lg = lane >> 4, li = lane & 15;
    int d = blockIdx.x * 8 + warp;

    float2 acc[4];
#pragma unroll
    for (int j = 0; j < 4; j++) acc[j] = make_float2(0.f, 0.f);

    if (d < NN) {
        int start = __ldg(&csr_start[d]);
        int end   = __ldg(&csr_start[d + 1]);
        for (int i = start; i < end; i += 4) {
            int e0 = i + lg;
            int e1 = i + lg + 2;
            if (e0 < end) {
                int s = __ldg(&csr_src[e0]);
                float w = __ldg(&cs[s]);
                uint4 u = __ldg((const uint4*)(hs + (size_t)s * HID) + li);
                float2 f;
                f = __half22float2(*reinterpret_cast<__half2*>(&u.x));
                acc[0].x = fmaf(f.x, w, acc[0].x); acc[0].y = fmaf(f.y, w, acc[0].y);
                f = __half22float2(*reinterpret_cast<__half2*>(&u.y));
                acc[1].x = fmaf(f.x, w, acc[1].x); acc[1].y = fmaf(f.y, w, acc[1].y);
                f = __half22float2(*reinterpret_cast<__half2*>(&u.z));
                acc[2].x = fmaf(f.x, w, acc[2].x); acc[2].y = fmaf(f.y, w, acc[2].y);
                f = __half22float2(*reinterpret_cast<__half2*>(&u.w));
                acc[3].x = fmaf(f.x, w, acc[3].x); acc[3].y = fmaf(f.y, w, acc[3].y);
            }
            if (e1 < end) {
                int s = __ldg(&csr_src[e1]);
                float w = __ldg(&cs[s]);
                uint4 u = __ldg((const uint4*)(hs + (size_t)s * HID) + li);
                float2 f;
                f = __half22float2(*reinterpret_cast<__half2*>(&u.x));
                acc[0].x = fmaf(f.x, w, acc[0].x); acc[0].y = fmaf(f.y, w, acc[0].y);
                f = __half22float2(*reinterpret_cast<__half2*>(&u.y));
                acc[1].x = fmaf(f.x, w, acc[1].x); acc[1].y = fmaf(f.y, w, acc[1].y);
                f = __half22float2(*reinterpret_cast<__half2*>(&u.z));
                acc[2].x = fmaf(f.x, w, acc[2].x); acc[2].y = fmaf(f.y, w, acc[2].y);
                f = __half22float2(*reinterpret_cast<__half2*>(&u.w));
                acc[3].x = fmaf(f.x, w, acc[3].x); acc[3].y = fmaf(f.y, w, acc[3].y);
            }
        }
#pragma unroll
        for (int j = 0; j < 4; j++) {
            acc[j].x += __shfl_xor_sync(0xffffffffu, acc[j].x, 16);
            acc[j].y += __shfl_xor_sync(0xffffffffu, acc[j].y, 16);
        }
        float c = __ldg(&cd[d]);
#pragma unroll
        for (int j = 0; j < 4; j++) { acc[j].x *= c; acc[j].y *= c; }
        if (lg == 0) {
            float4 o0 = make_float4(acc[0].x, acc[0].y, acc[1].x, acc[1].y);
            float4 o1 = make_float4(acc[2].x, acc[2].y, acc[3].x, acc[3].y);
            *(float4*)(y + (size_t)d * HID + li * 8)     = o0;
            *(float4*)(y + (size_t)d * HID + li * 8 + 4) = o1;
        }
    }

    if (lg == 0) {
#pragma unroll
        for (int j = 0; j < 4; j++) {
            int c0 = li * 8 + 2 * j;
            float vx = (d < NN) ? acc[j].x : 0.f;
            float vy = (d < NN) ? acc[j].y : 0.f;
            s_sum[warp][c0]     = vx;
            s_sum[warp][c0 + 1] = vy;
            s_sq [warp][c0]     = vx * vx;
            s_sq [warp][c0 + 1] = vy * vy;
        }
    }
    __syncthreads();

    int t = threadIdx.x;
    if (t < HID) {
        float s = 0.f;
#pragma unroll
        for (int w = 0; w < 8; w++) s += s_sum[w][t];
        atomicAdd(&stats[t], s);
    } else {
        int c = t - HID;
        float s = 0.f;
#pragma unroll
        for (int w = 0; w < 8; w++) s += s_sq[w][c];
        atomicAdd(&stats[HID + c], s);
    }
}

// ---------------------------------------------------------------------------
// Readout: block per graph, 256 threads = 128 channels x 2 row-phases.
// Phase split halves the serial row loop; combine via smem.
// ---------------------------------------------------------------------------
__global__ void __launch_bounds__(256)
k_readout(const float* __restrict__ y, const float* __restrict__ stats,
          const float* __restrict__ gw, const float* __restrict__ gb,
          const float* __restrict__ gs, const int* __restrict__ gstart,
          float* __restrict__ out, int layer) {
    __shared__ float s_r0[256], s_r1[256], s_r2[256];
    int g = blockIdx.x;
    int t = threadIdx.x;
    int c = t & 127, ph = t >> 7;
    float a, b;
    alpha_beta(stats, gw, gb, gs, c, a, b);
    int s0 = gstart[g], s1 = gstart[g + 1];
    float sum = 0.f, mx = -CUDART_INF_F, mn = CUDART_INF_F;
    for (int r = s0 + ph; r < s1; r += 2) {
        float v = leaky(__ldg(&y[(size_t)r * HID + c]) * a + b);
        sum += v;
        mx = fmaxf(mx, v);
        mn = fminf(mn, v);
    }
    s_r0[t] = sum; s_r1[t] = mx; s_r2[t] = mn;
    __syncthreads();
    if (ph == 0) {
        sum += s_r0[t + 128];
        mx = fmaxf(mx, s_r1[t + 128]);
        mn = fminf(mn, s_r2[t + 128]);
        int cnt = s1 - s0;
        float mean = sum / fmaxf((float)cnt, 1.f);
        if (cnt == 0) { mx = 0.f; mn = 0.f; }
        float* o = out + (size_t)g * (9 * HID) + layer * (3 * HID);
        o[c]           = leaky(mean);
        o[HID + c]     = leaky(mx);
        o[2 * HID + c] = leaky(mn);
    }
}

// ---------------------------------------------------------------------------
// Launch: single stream, 15 launches
// ---------------------------------------------------------------------------
extern "C" void kernel_launch(void* const* d_in, const int* in_sizes, int n_in,
                              void* d_out, int out_size) {
    const float* X   = (const float*)d_in[0];
    const float* W1  = (const float*)d_in[1];
    const float* W2  = (const float*)d_in[2];
    const float* W3  = (const float*)d_in[3];
    const float* gw  = (const float*)d_in[4];
    const float* gb  = (const float*)d_in[5];
    const float* gs  = (const float*)d_in[6];
    const int*   src = (const int*)d_in[7];
    const int*   dst = (const int*)d_in[8];
    const int*   gid = (const int*)d_in[9];
    float* out = (float*)d_out;

    __half* hs;
    float *y, *cs, *cd, *stats;
    int *deg, *gstart, *csr_start, *cursor, *csr_src, *bsum;
    cudaGetSymbolAddress((void**)&hs,        g_hs);
    cudaGetSymbolAddress((void**)&y,         g_y);
    cudaGetSymbolAddress((void**)&cs,        g_cs);
    cudaGetSymbolAddress((void**)&cd,        g_cd);
    cudaGetSymbolAddress((void**)&stats,     g_stats);
    cudaGetSymbolAddress((void**)&deg,       g_deg);
    cudaGetSymbolAddress((void**)&gstart,    g_gstart);
    cudaGetSymbolAddress((void**)&csr_start, g_csr_start);
    cudaGetSymbolAddress((void**)&cursor,    g_cursor);
    cudaGetSymbolAddress((void**)&csr_src,   g_csr_src);
    cudaGetSymbolAddress((void**)&bsum,      g_bsum);

    // --- setup: degrees, segment starts, dst-CSR (6 launches) ---
    k_setup_zero<<<256, 256>>>(deg, stats);
    k_degrees<<<(EE + 255) / 256, 256>>>(src, dst, deg);
    k_misc<<<NB_SCAN, 256>>>(deg, gid, cs, cd, gstart, bsum);
    k_scan2<<<1, 256>>>(bsum);
    k_scan3<<<NB_SCAN, 256>>>(deg + NN, bsum, csr_start, cursor);
    k_fill_csr<<<(EE + 255) / 256, 256>>>(src, dst, cursor, csr_src);

    const float* Wl[3] = {W1, W2, W3};
    const int gemm_grid = (NN + 63) / 64;
    const int agg_grid  = (NN + 7) / 8;

    for (int L = 0; L < 3; L++) {
        if (L == 0)
            k_gemm<INF_, false><<<gemm_grid, 256>>>(
                X, Wl[0], nullptr, nullptr, nullptr, nullptr, hs);
        else
            k_gemm<HID, true><<<gemm_grid, 256>>>(
                y, Wl[L], stats + (L - 1) * 2 * HID,
                gw + (L - 1) * HID, gb + (L - 1) * HID, gs + (L - 1) * HID, hs);

        k_aggstats<<<agg_grid, 256>>>(hs, csr_start, csr_src, cs, cd, y,
                                      stats + L * 2 * HID);

        k_readout<<<GG, 256>>>(y, stats + L * 2 * HID, gw + L * HID,
                               gb + L * HID, gs + L * HID, gstart, out, L);
    }
}

// round 11
// speedup vs baseline: 1.0660x; 1.0059x over previous
#include <cuda_runtime.h>
#include <cuda_fp16.h>
#include <math_constants.h>
#include <cstdint>

// Problem constants (fixed by the dataset)
#define NN   50000
#define EE   600000
#define GG   1000
#define HID  128
#define INF_ 64
#define EPS  1e-5f
#define SLOPE 0.01f

#define NB_SCAN ((NN + 255) / 256)   // 196
#define BUF_E 8                      // edges per TMA batch per warp

// ---------------------------------------------------------------------------
// Scratch (static __device__ arrays; no allocation anywhere)
// ---------------------------------------------------------------------------
__device__ __align__(256) __half g_hs [NN * HID];  // (x@W)*cs fp16, 256B rows
__device__ float  g_y  [NN * HID];
__device__ float  g_cs [NN];
__device__ float  g_cd [NN];
__device__ int    g_deg[2 * NN];
__device__ int    g_csr_start[NN + 1];
__device__ int    g_cursor[NN];
__device__ int    g_csr_src[EE];
__device__ int    g_bsum[256];
__device__ float  g_stats[3 * 2 * HID];
__device__ int    g_gstart[GG + 1];

__device__ __forceinline__ float leaky(float v) { return v > 0.f ? v : SLOPE * v; }

__device__ __forceinline__ void alpha_beta(const float* __restrict__ stats,
                                           const float* __restrict__ gw,
                                           const float* __restrict__ gb,
                                           const float* __restrict__ gs,
                                           int c, float& a, float& b) {
    float m   = stats[c] * (1.f / (float)NN);
    float ex2 = stats[HID + c] * (1.f / (float)NN);
    float s   = gs[c];
    float var = ex2 - m * m * (2.f * s - s * s);
    float inv = rsqrtf(var + EPS);
    a = inv * gw[c];
    b = gb[c] - s * m * a;
}

// packed f32x2 helpers
__device__ __forceinline__ unsigned long long pack2(float x, float y) {
    unsigned long long r;
    asm("mov.b64 %0, {%1, %2};" : "=l"(r) : "f"(x), "f"(y));
    return r;
}
__device__ __forceinline__ void unpack2(unsigned long long p, float& x, float& y) {
    asm("mov.b64 {%0, %1}, %2;" : "=f"(x), "=f"(y) : "l"(p));
}
__device__ __forceinline__ void fma2(unsigned long long& d, unsigned long long a,
                                     unsigned long long b) {
    asm("fma.rn.f32x2 %0, %1, %2, %0;" : "+l"(d) : "l"(a), "l"(b));
}

__device__ __forceinline__ uint32_t smem_u32(const void* p) {
    return (uint32_t)__cvta_generic_to_shared(p);
}
__device__ __forceinline__ void mbar_wait(uint32_t mbar, uint32_t parity) {
    asm volatile(
        "{\n\t.reg .pred P1;\n\t"
        "W_%=:\n\t"
        "mbarrier.try_wait.parity.acquire.cta.shared::cta.b64 P1, [%0], %1, 0x989680;\n\t"
        "@P1 bra.uni D_%=;\n\t"
        "bra.uni W_%=;\n\t"
        "D_%=:\n\t}"
        :: "r"(mbar), "r"(parity) : "memory");
}

// ---------------------------------------------------------------------------
// Setup kernels (round-10 proven)
// ---------------------------------------------------------------------------
__global__ void k_setup_zero(int* __restrict__ deg, float* __restrict__ stats) {
    int i = blockIdx.x * blockDim.x + threadIdx.x;
    int stride = gridDim.x * blockDim.x;
    for (int j = i; j < 2 * NN; j += stride) deg[j] = 0;
    for (int j = i; j < 3 * 2 * HID; j += stride) stats[j] = 0.f;
}

__global__ void k_degrees(const int* __restrict__ src, const int* __restrict__ dst,
                          int* __restrict__ deg) {
    int e = blockIdx.x * blockDim.x + threadIdx.x;
    if (e >= EE) return;
    atomicAdd(&deg[src[e]], 1);
    atomicAdd(&deg[NN + dst[e]], 1);
}

__global__ void k_misc(const int* __restrict__ deg, const int* __restrict__ gid,
                       float* __restrict__ cs, float* __restrict__ cd,
                       int* __restrict__ gstart, int* __restrict__ bsum) {
    __shared__ int sh[256];
    int t = threadIdx.x;
    int i = blockIdx.x * 256 + t;
    int v = 0;
    if (i < NN) {
        int od = deg[i], id = deg[NN + i];
        cs[i] = rsqrtf(fmaxf((float)od, 1.f));
        cd[i] = rsqrtf(fmaxf((float)id, 1.f));
        v = id;
        int g  = gid[i];
        int gp = (i == 0) ? -1 : gid[i - 1];
        for (int gg = gp + 1; gg <= g; gg++) gstart[gg] = i;
        if (i == NN - 1)
            for (int gg = g + 1; gg <= GG; gg++) gstart[gg] = NN;
    }
    sh[t] = v;
    __syncthreads();
    for (int o = 128; o > 0; o >>= 1) {
        if (t < o) sh[t] += sh[t + o];
        __syncthreads();
    }
    if (t == 0) bsum[blockIdx.x] = sh[0];
}

__global__ void k_scan2(int* __restrict__ bsum) {
    __shared__ int sh[256];
    int tid = threadIdx.x;
    int v = (tid < NB_SCAN) ? bsum[tid] : 0;
    sh[tid] = v;
    __syncthreads();
    for (int o = 1; o < 256; o <<= 1) {
        int t = (tid >= o) ? sh[tid - o] : 0;
        __syncthreads();
        sh[tid] += t;
        __syncthreads();
    }
    if (tid < NB_SCAN) bsum[tid] = sh[tid] - v;
}

__global__ void k_scan3(const int* __restrict__ indeg, const int* __restrict__ bsum,
                        int* __restrict__ csr_start, int* __restrict__ cursor) {
    __shared__ int sh[256];
    int tid = threadIdx.x;
    int i = blockIdx.x * 256 + tid;
    int v = (i < NN) ? indeg[i] : 0;
    sh[tid] = v;
    __syncthreads();
    for (int o = 1; o < 256; o <<= 1) {
        int t = (tid >= o) ? sh[tid - o] : 0;
        __syncthreads();
        sh[tid] += t;
        __syncthreads();
    }
    int excl = sh[tid] - v + bsum[blockIdx.x];
    if (i < NN) { csr_start[i] = excl; cursor[i] = excl; }
    if (i == NN - 1) csr_start[NN] = excl + v;
}

__global__ void k_fill_csr(const int* __restrict__ src, const int* __restrict__ dst,
                           int* __restrict__ cursor, int* __restrict__ csr_src) {
    int e = blockIdx.x * blockDim.x + threadIdx.x;
    if (e >= EE) return;
    int pos = atomicAdd(&cursor[dst[e]], 1);
    csr_src[pos] = src[e];
}

// ---------------------------------------------------------------------------
// Packed-f32x2 GEMM: hs[N,128] = (f(X)[N,K] @ W[K,128]) * cs[row], fp16 out.
// cs folded back into epilogue (gather is now a pure sum).
// ---------------------------------------------------------------------------
template <int K, bool NORM>
__global__ void __launch_bounds__(256, 2)
k_gemm(const float* __restrict__ X, const float* __restrict__ W,
       const float* __restrict__ cs,
       const float* __restrict__ stats, const float* __restrict__ gw,
       const float* __restrict__ gb, const float* __restrict__ gs,
       __half* __restrict__ out) {
    constexpr int BK = 32;
    __shared__ float Ws[BK][HID];
    __shared__ float Xs[BK][68];
    __shared__ float s_a[HID], s_b[HID];

    int tid = threadIdx.x;
    int tx = tid & 31, ty = tid >> 5;
    int row0 = blockIdx.x * 64;
    int rb = ty * 8, cb = tx * 4;

    if (NORM) {
        if (tid < HID) {
            float a, b;
            alpha_beta(stats, gw, gb, gs, tid, a, b);
            s_a[tid] = a;
            s_b[tid] = b;
        }
        __syncthreads();
    }

    unsigned long long acc[4][4];
#pragma unroll
    for (int i = 0; i < 4; i++)
#pragma unroll
        for (int j = 0; j < 4; j++) acc[i][j] = 0ull;

    for (int k0 = 0; k0 < K; k0 += BK) {
        for (int i = tid; i < BK * 32; i += 256) {
            int k = i >> 5, c = (i & 31) * 4;
            *(float4*)&Ws[k][c] = *(const float4*)&W[(k0 + k) * HID + c];
        }
        for (int i = tid; i < 64 * 8; i += 256) {
            int r = i >> 3, kq = (i & 7) * 4;
            int g = row0 + r;
            float4 v = make_float4(0.f, 0.f, 0.f, 0.f);
            if (g < NN) v = *(const float4*)&X[(size_t)g * K + k0 + kq];
            if (NORM) {
                float4 a = *(const float4*)&s_a[k0 + kq];
                float4 b = *(const float4*)&s_b[k0 + kq];
                v.x = leaky(v.x * a.x + b.x);
                v.y = leaky(v.y * a.y + b.y);
                v.z = leaky(v.z * a.z + b.z);
                v.w = leaky(v.w * a.w + b.w);
            }
            Xs[kq + 0][r] = v.x;
            Xs[kq + 1][r] = v.y;
            Xs[kq + 2][r] = v.z;
            Xs[kq + 3][r] = v.w;
        }
        __syncthreads();

#pragma unroll
        for (int k = 0; k < BK; k++) {
            ulonglong2 xa = *(const ulonglong2*)&Xs[k][rb];
            ulonglong2 xb = *(const ulonglong2*)&Xs[k][rb + 4];
            float4 w = *(const float4*)&Ws[k][cb];
            unsigned long long w0 = pack2(w.x, w.x);
            unsigned long long w1 = pack2(w.y, w.y);
            unsigned long long w2 = pack2(w.z, w.z);
            unsigned long long w3 = pack2(w.w, w.w);
            fma2(acc[0][0], xa.x, w0); fma2(acc[0][1], xa.x, w1);
            fma2(acc[0][2], xa.x, w2); fma2(acc[0][3], xa.x, w3);
            fma2(acc[1][0], xa.y, w0); fma2(acc[1][1], xa.y, w1);
            fma2(acc[1][2], xa.y, w2); fma2(acc[1][3], xa.y, w3);
            fma2(acc[2][0], xb.x, w0); fma2(acc[2][1], xb.x, w1);
            fma2(acc[2][2], xb.x, w2); fma2(acc[2][3], xb.x, w3);
            fma2(acc[3][0], xb.y, w0); fma2(acc[3][1], xb.y, w1);
            fma2(acc[3][2], xb.y, w2); fma2(acc[3][3], xb.y, w3);
        }
        __syncthreads();
    }

#pragma unroll
    for (int rp = 0; rp < 4; rp++) {
        float lo[4], hi[4];
#pragma unroll
        for (int c = 0; c < 4; c++) unpack2(acc[rp][c], lo[c], hi[c]);
        int g0 = row0 + rb + 2 * rp;
        int g1 = g0 + 1;
        if (g0 < NN) {
            float c0 = __ldg(&cs[g0]);
            __half2 p0 = __floats2half2_rn(lo[0] * c0, lo[1] * c0);
            __half2 p1 = __floats2half2_rn(lo[2] * c0, lo[3] * c0);
            uint2 u;
            u.x = *reinterpret_cast<uint32_t*>(&p0);
            u.y = *reinterpret_cast<uint32_t*>(&p1);
            *(uint2*)&out[(size_t)g0 * HID + cb] = u;
        }
        if (g1 < NN) {
            float c1 = __ldg(&cs[g1]);
            __half2 p0 = __floats2half2_rn(hi[0] * c1, hi[1] * c1);
            __half2 p1 = __floats2half2_rn(hi[2] * c1, hi[3] * c1);
            uint2 u;
            u.x = *reinterpret_cast<uint32_t*>(&p0);
            u.y = *reinterpret_cast<uint32_t*>(&p1);
            *(uint2*)&out[(size_t)g1 * HID + cb] = u;
        }
    }
}

// ---------------------------------------------------------------------------
// TMA-bulk aggregation: warp per dst node. Batches of <=8 in-edge rows are
// pulled to smem via cp.async.bulk (one instr per 256B row; LTS path, not
// LSU), completion via per-warp mbarrier tx-count; rows summed from smem.
// y = sum * cd ; column stats reduced block-wide -> one atomic per channel.
// ---------------------------------------------------------------------------
__global__ void __launch_bounds__(256)
k_aggstats(const __half* __restrict__ hs, const int* __restrict__ csr_start,
           const int* __restrict__ csr_src, const float* __restrict__ cd,
           float* __restrict__ y, float* __restrict__ stats) {
    __shared__ __align__(16) char buf[8][BUF_E * 256];   // 16 KB
    __shared__ __align__(8) uint64_t mbar[8];
    __shared__ float s_sum[8][HID];
    __shared__ float s_sq [8][HID];

    int warp = threadIdx.x >> 5, lane = threadIdx.x & 31;
    int lg = lane >> 4, li = lane & 15;
    int d = blockIdx.x * 8 + warp;
    uint32_t mb = smem_u32(&mbar[warp]);

    if (lane == 0)
        asm volatile("mbarrier.init.shared.b64 [%0], 1;" :: "r"(mb) : "memory");
    __syncwarp();

    float2 acc[4];
#pragma unroll
    for (int j = 0; j < 4; j++) acc[j] = make_float2(0.f, 0.f);

    if (d < NN) {
        int start = __ldg(&csr_start[d]);
        int end   = __ldg(&csr_start[d + 1]);
        uint32_t parity = 0;
        for (int i = start; i < end; i += BUF_E) {
            int cnt = min(BUF_E, end - i);
            if (lane == 0)
                asm volatile(
                    "mbarrier.arrive.expect_tx.shared.b64 _, [%0], %1;"
                    :: "r"(mb), "r"((uint32_t)(cnt * 256)) : "memory");
            __syncwarp();
            if (lane < cnt) {
                int s = __ldg(&csr_src[i + lane]);
                uint32_t dst = smem_u32(&buf[warp][lane * 256]);
                const void* gsrc = hs + (size_t)s * HID;
                asm volatile(
                    "cp.async.bulk.shared::cluster.global.mbarrier::complete_tx::bytes "
                    "[%0], [%1], %2, [%3];"
                    :: "r"(dst), "l"(gsrc), "r"(256u), "r"(mb) : "memory");
            }
            mbar_wait(mb, parity);
            parity ^= 1u;
            // sum cnt rows from smem: lane-group lg handles rows lg, lg+2, ...
            for (int j = lg; j < cnt; j += 2) {
                uint4 u = *(const uint4*)&buf[warp][j * 256 + li * 16];
                float2 f;
                f = __half22float2(*reinterpret_cast<__half2*>(&u.x));
                acc[0].x += f.x; acc[0].y += f.y;
                f = __half22float2(*reinterpret_cast<__half2*>(&u.y));
                acc[1].x += f.x; acc[1].y += f.y;
                f = __half22float2(*reinterpret_cast<__half2*>(&u.z));
                acc[2].x += f.x; acc[2].y += f.y;
                f = __half22float2(*reinterpret_cast<__half2*>(&u.w));
                acc[3].x += f.x; acc[3].y += f.y;
            }
            __syncwarp();   // all lanes done reading buf before next batch
        }
#pragma unroll
        for (int j = 0; j < 4; j++) {
            acc[j].x += __shfl_xor_sync(0xffffffffu, acc[j].x, 16);
            acc[j].y += __shfl_xor_sync(0xffffffffu, acc[j].y, 16);
        }
        float c = __ldg(&cd[d]);
#pragma unroll
        for (int j = 0; j < 4; j++) { acc[j].x *= c; acc[j].y *= c; }
        if (lg == 0) {
            float4 o0 = make_float4(acc[0].x, acc[0].y, acc[1].x, acc[1].y);
            float4 o1 = make_float4(acc[2].x, acc[2].y, acc[3].x, acc[3].y);
            *(float4*)(y + (size_t)d * HID + li * 8)     = o0;
            *(float4*)(y + (size_t)d * HID + li * 8 + 4) = o1;
        }
    }

    if (lg == 0) {
#pragma unroll
        for (int j = 0; j < 4; j++) {
            int c0 = li * 8 + 2 * j;
            float vx = (d < NN) ? acc[j].x : 0.f;
            float vy = (d < NN) ? acc[j].y : 0.f;
            s_sum[warp][c0]     = vx;
            s_sum[warp][c0 + 1] = vy;
            s_sq [warp][c0]     = vx * vx;
            s_sq [warp][c0 + 1] = vy * vy;
        }
    }
    __syncthreads();

    int t = threadIdx.x;
    if (t < HID) {
        float s = 0.f;
#pragma unroll
        for (int w = 0; w < 8; w++) s += s_sum[w][t];
        atomicAdd(&stats[t], s);
    } else {
        int c = t - HID;
        float s = 0.f;
#pragma unroll
        for (int w = 0; w < 8; w++) s += s_sq[w][c];
        atomicAdd(&stats[HID + c], s);
    }
}

// ---------------------------------------------------------------------------
// Readout: block per graph, 256 threads = 128 channels x 2 row-phases.
// ---------------------------------------------------------------------------
__global__ void __launch_bounds__(256)
k_readout(const float* __restrict__ y, const float* __restrict__ stats,
          const float* __restrict__ gw, const float* __restrict__ gb,
          const float* __restrict__ gs, const int* __restrict__ gstart,
          float* __restrict__ out, int layer) {
    __shared__ float s_r0[256], s_r1[256], s_r2[256];
    int g = blockIdx.x;
    int t = threadIdx.x;
    int c = t & 127, ph = t >> 7;
    float a, b;
    alpha_beta(stats, gw, gb, gs, c, a, b);
    int s0 = gstart[g], s1 = gstart[g + 1];
    float sum = 0.f, mx = -CUDART_INF_F, mn = CUDART_INF_F;
    for (int r = s0 + ph; r < s1; r += 2) {
        float v = leaky(__ldg(&y[(size_t)r * HID + c]) * a + b);
        sum += v;
        mx = fmaxf(mx, v);
        mn = fminf(mn, v);
    }
    s_r0[t] = sum; s_r1[t] = mx; s_r2[t] = mn;
    __syncthreads();
    if (ph == 0) {
        sum += s_r0[t + 128];
        mx = fmaxf(mx, s_r1[t + 128]);
        mn = fminf(mn, s_r2[t + 128]);
        int cnt = s1 - s0;
        float mean = sum / fmaxf((float)cnt, 1.f);
        if (cnt == 0) { mx = 0.f; mn = 0.f; }
        float* o = out + (size_t)g * (9 * HID) + layer * (3 * HID);
        o[c]           = leaky(mean);
        o[HID + c]     = leaky(mx);
        o[2 * HID + c] = leaky(mn);
    }
}

// ---------------------------------------------------------------------------
// Launch: single stream, 15 launches
// ---------------------------------------------------------------------------
extern "C" void kernel_launch(void* const* d_in, const int* in_sizes, int n_in,
                              void* d_out, int out_size) {
    const float* X   = (const float*)d_in[0];
    const float* W1  = (const float*)d_in[1];
    const float* W2  = (const float*)d_in[2];
    const float* W3  = (const float*)d_in[3];
    const float* gw  = (const float*)d_in[4];
    const float* gb  = (const float*)d_in[5];
    const float* gs  = (const float*)d_in[6];
    const int*   src = (const int*)d_in[7];
    const int*   dst = (const int*)d_in[8];
    const int*   gid = (const int*)d_in[9];
    float* out = (float*)d_out;

    __half* hs;
    float *y, *cs, *cd, *stats;
    int *deg, *gstart, *csr_start, *cursor, *csr_src, *bsum;
    cudaGetSymbolAddress((void**)&hs,        g_hs);
    cudaGetSymbolAddress((void**)&y,         g_y);
    cudaGetSymbolAddress((void**)&cs,        g_cs);
    cudaGetSymbolAddress((void**)&cd,        g_cd);
    cudaGetSymbolAddress((void**)&stats,     g_stats);
    cudaGetSymbolAddress((void**)&deg,       g_deg);
    cudaGetSymbolAddress((void**)&gstart,    g_gstart);
    cudaGetSymbolAddress((void**)&csr_start, g_csr_start);
    cudaGetSymbolAddress((void**)&cursor,    g_cursor);
    cudaGetSymbolAddress((void**)&csr_src,   g_csr_src);
    cudaGetSymbolAddress((void**)&bsum,      g_bsum);

    // --- setup ---
    k_setup_zero<<<256, 256>>>(deg, stats);
    k_degrees<<<(EE + 255) / 256, 256>>>(src, dst, deg);
    k_misc<<<NB_SCAN, 256>>>(deg, gid, cs, cd, gstart, bsum);
    k_scan2<<<1, 256>>>(bsum);
    k_scan3<<<NB_SCAN, 256>>>(deg + NN, bsum, csr_start, cursor);
    k_fill_csr<<<(EE + 255) / 256, 256>>>(src, dst, cursor, csr_src);

    const float* Wl[3] = {W1, W2, W3};
    const int gemm_grid = (NN + 63) / 64;
    const int agg_grid  = (NN + 7) / 8;

    for (int L = 0; L < 3; L++) {
        if (L == 0)
            k_gemm<INF_, false><<<gemm_grid, 256>>>(
                X, Wl[0], cs, nullptr, nullptr, nullptr, nullptr, hs);
        else
            k_gemm<HID, true><<<gemm_grid, 256>>>(
                y, Wl[L], cs, stats + (L - 1) * 2 * HID,
                gw + (L - 1) * HID, gb + (L - 1) * HID, gs + (L - 1) * HID, hs);

        k_aggstats<<<agg_grid, 256>>>(hs, csr_start, csr_src, cd, y,
                                      stats + L * 2 * HID);

        k_readout<<<GG, 256>>>(y, stats + L * 2 * HID, gw + L * HID,
                               gb + L * HID, gs + L * HID, gstart, out, L);
    }
}

// round 13
// speedup vs baseline: 1.0975x; 1.0296x over previous
#include <cuda_runtime.h>
#include <cuda_fp16.h>
#include <math_constants.h>
#include <cstdint>

// Problem constants (fixed by the dataset)
#define NN   50000
#define EE   600000
#define GG   1000
#define HID  128
#define INF_ 64
#define EPS  1e-5f
#define SLOPE 0.01f

#define NB_SCAN ((NN + 255) / 256)   // 196
#define BUF_E 8                      // edges per TMA batch per warp
#define GEMM_GRID ((NN + 63) / 64)   // 782

// ---------------------------------------------------------------------------
// Scratch (static __device__ arrays; no allocation anywhere)
// ---------------------------------------------------------------------------
__device__ __align__(256) __half g_hs [NN * HID];  // (x@W)*cs fp16, 256B rows
__device__ float  g_y  [NN * HID];
__device__ float  g_cs [NN];
__device__ float  g_cd [NN];
__device__ int    g_deg[2 * NN];     // [0,N): outdeg, [N,2N): indeg
__device__ int    g_csr_start[NN];   // segment base per node (non-monotonic)
__device__ int    g_cursor[NN];
__device__ int    g_csr_src[EE];
__device__ int    g_total[1];        // atomic segment allocator
__device__ float  g_stats[3 * 2 * HID];
__device__ int    g_gstart[GG + 1];

__device__ __forceinline__ float leaky(float v) { return v > 0.f ? v : SLOPE * v; }

__device__ __forceinline__ void alpha_beta(const float* __restrict__ stats,
                                           const float* __restrict__ gw,
                                           const float* __restrict__ gb,
                                           const float* __restrict__ gs,
                                           int c, float& a, float& b) {
    float m   = stats[c] * (1.f / (float)NN);
    float ex2 = stats[HID + c] * (1.f / (float)NN);
    float s   = gs[c];
    float var = ex2 - m * m * (2.f * s - s * s);
    float inv = rsqrtf(var + EPS);
    a = inv * gw[c];
    b = gb[c] - s * m * a;
}

// packed f32x2 helpers
__device__ __forceinline__ unsigned long long pack2(float x, float y) {
    unsigned long long r;
    asm("mov.b64 %0, {%1, %2};" : "=l"(r) : "f"(x), "f"(y));
    return r;
}
__device__ __forceinline__ void unpack2(unsigned long long p, float& x, float& y) {
    asm("mov.b64 {%0, %1}, %2;" : "=f"(x), "=f"(y) : "l"(p));
}
__device__ __forceinline__ void fma2(unsigned long long& d, unsigned long long a,
                                     unsigned long long b) {
    asm("fma.rn.f32x2 %0, %1, %2, %0;" : "+l"(d) : "l"(a), "l"(b));
}

__device__ __forceinline__ uint32_t smem_u32(const void* p) {
    return (uint32_t)__cvta_generic_to_shared(p);
}
__device__ __forceinline__ void mbar_wait(uint32_t mbar, uint32_t parity) {
    asm volatile(
        "{\n\t.reg .pred P1;\n\t"
        "W_%=:\n\t"
        "mbarrier.try_wait.parity.acquire.cta.shared::cta.b64 P1, [%0], %1, 0x989680;\n\t"
        "@P1 bra.uni D_%=;\n\t"
        "bra.uni W_%=;\n\t"
        "D_%=:\n\t}"
        :: "r"(mbar), "r"(parity) : "memory");
}

// ---------------------------------------------------------------------------
// Setup: zero deg + stats + segment allocator
// ---------------------------------------------------------------------------
__global__ void k_setup_zero(int* __restrict__ deg, float* __restrict__ stats,
                             int* __restrict__ total) {
    int i = blockIdx.x * blockDim.x + threadIdx.x;
    int stride = gridDim.x * blockDim.x;
    for (int j = i; j < 2 * NN; j += stride) deg[j] = 0;
    for (int j = i; j < 3 * 2 * HID; j += stride) stats[j] = 0.f;
    if (i == 0) total[0] = 0;
}

__global__ void k_degrees(const int* __restrict__ src, const int* __restrict__ dst,
                          int* __restrict__ deg) {
    int e = blockIdx.x * blockDim.x + threadIdx.x;
    if (e >= EE) return;
    atomicAdd(&deg[src[e]], 1);
    atomicAdd(&deg[NN + dst[e]], 1);
}

// ---------------------------------------------------------------------------
// Fused post-degree setup: invdeg + gstart + CSR segment assignment via
// block-local scan + one global atomicAdd (ordering across blocks is
// irrelevant: segments only need to be disjoint and sized by indeg).
// ---------------------------------------------------------------------------
__global__ void k_misc(const int* __restrict__ deg, const int* __restrict__ gid,
                       float* __restrict__ cs, float* __restrict__ cd,
                       int* __restrict__ gstart, int* __restrict__ csr_start,
                       int* __restrict__ cursor, int* __restrict__ total) {
    __shared__ int sh[256];
    __shared__ int s_base;
    int t = threadIdx.x;
    int i = blockIdx.x * 256 + t;
    int v = 0;
    if (i < NN) {
        int od = deg[i], id = deg[NN + i];
        cs[i] = rsqrtf(fmaxf((float)od, 1.f));
        cd[i] = rsqrtf(fmaxf((float)id, 1.f));
        v = id;
        int g  = gid[i];
        int gp = (i == 0) ? -1 : gid[i - 1];
        for (int gg = gp + 1; gg <= g; gg++) gstart[gg] = i;
        if (i == NN - 1)
            for (int gg = g + 1; gg <= GG; gg++) gstart[gg] = NN;
    }
    sh[t] = v;
    __syncthreads();
    // inclusive scan within block
    for (int o = 1; o < 256; o <<= 1) {
        int tv = (t >= o) ? sh[t - o] : 0;
        __syncthreads();
        sh[t] += tv;
        __syncthreads();
    }
    if (t == 255) s_base = atomicAdd(total, sh[255]);
    __syncthreads();
    if (i < NN) {
        int start = s_base + sh[t] - v;   // exclusive within block + block base
        csr_start[i] = start;
        cursor[i] = start;
    }
}

__global__ void k_fill_csr(const int* __restrict__ src, const int* __restrict__ dst,
                           int* __restrict__ cursor, int* __restrict__ csr_src) {
    int e = blockIdx.x * blockDim.x + threadIdx.x;
    if (e >= EE) return;
    int pos = atomicAdd(&cursor[dst[e]], 1);
    csr_src[pos] = src[e];
}

// ---------------------------------------------------------------------------
// GEMM device body (packed f32x2, round-8 proven): block covers 64 rows.
// ---------------------------------------------------------------------------
template <int K, bool NORM>
__device__ __forceinline__ void gemm_body(
    int blk, const float* __restrict__ X, const float* __restrict__ W,
    const float* __restrict__ cs, const float* __restrict__ s_a,
    const float* __restrict__ s_b, __half* __restrict__ out,
    float (*Ws)[HID], float (*Xs)[68]) {
    int tid = threadIdx.x;
    int tx = tid & 31, ty = tid >> 5;
    int row0 = blk * 64;
    int rb = ty * 8, cb = tx * 4;

    unsigned long long acc[4][4];
#pragma unroll
    for (int i = 0; i < 4; i++)
#pragma unroll
        for (int j = 0; j < 4; j++) acc[i][j] = 0ull;

    for (int k0 = 0; k0 < K; k0 += 32) {
        for (int i = tid; i < 32 * 32; i += 256) {
            int k = i >> 5, c = (i & 31) * 4;
            *(float4*)&Ws[k][c] = *(const float4*)&W[(k0 + k) * HID + c];
        }
        for (int i = tid; i < 64 * 8; i += 256) {
            int r = i >> 3, kq = (i & 7) * 4;
            int g = row0 + r;
            float4 v = make_float4(0.f, 0.f, 0.f, 0.f);
            if (g < NN) v = *(const float4*)&X[(size_t)g * K + k0 + kq];
            if (NORM) {
                float4 a = *(const float4*)&s_a[k0 + kq];
                float4 b = *(const float4*)&s_b[k0 + kq];
                v.x = leaky(v.x * a.x + b.x);
                v.y = leaky(v.y * a.y + b.y);
                v.z = leaky(v.z * a.z + b.z);
                v.w = leaky(v.w * a.w + b.w);
            }
            Xs[kq + 0][r] = v.x;
            Xs[kq + 1][r] = v.y;
            Xs[kq + 2][r] = v.z;
            Xs[kq + 3][r] = v.w;
        }
        __syncthreads();

#pragma unroll
        for (int k = 0; k < 32; k++) {
            ulonglong2 xa = *(const ulonglong2*)&Xs[k][rb];
            ulonglong2 xb = *(const ulonglong2*)&Xs[k][rb + 4];
            float4 w = *(const float4*)&Ws[k][cb];
            unsigned long long w0 = pack2(w.x, w.x);
            unsigned long long w1 = pack2(w.y, w.y);
            unsigned long long w2 = pack2(w.z, w.z);
            unsigned long long w3 = pack2(w.w, w.w);
            fma2(acc[0][0], xa.x, w0); fma2(acc[0][1], xa.x, w1);
            fma2(acc[0][2], xa.x, w2); fma2(acc[0][3], xa.x, w3);
            fma2(acc[1][0], xa.y, w0); fma2(acc[1][1], xa.y, w1);
            fma2(acc[1][2], xa.y, w2); fma2(acc[1][3], xa.y, w3);
            fma2(acc[2][0], xb.x, w0); fma2(acc[2][1], xb.x, w1);
            fma2(acc[2][2], xb.x, w2); fma2(acc[2][3], xb.x, w3);
            fma2(acc[3][0], xb.y, w0); fma2(acc[3][1], xb.y, w1);
            fma2(acc[3][2], xb.y, w2); fma2(acc[3][3], xb.y, w3);
        }
        __syncthreads();
    }

#pragma unroll
    for (int rp = 0; rp < 4; rp++) {
        float lo[4], hi[4];
#pragma unroll
        for (int c = 0; c < 4; c++) unpack2(acc[rp][c], lo[c], hi[c]);
        int g0 = row0 + rb + 2 * rp;
        int g1 = g0 + 1;
        if (g0 < NN) {
            float c0 = __ldg(&cs[g0]);
            __half2 p0 = __floats2half2_rn(lo[0] * c0, lo[1] * c0);
            __half2 p1 = __floats2half2_rn(lo[2] * c0, lo[3] * c0);
            uint2 u;
            u.x = *reinterpret_cast<uint32_t*>(&p0);
            u.y = *reinterpret_cast<uint32_t*>(&p1);
            *(uint2*)&out[(size_t)g0 * HID + cb] = u;
        }
        if (g1 < NN) {
            float c1 = __ldg(&cs[g1]);
            __half2 p0 = __floats2half2_rn(hi[0] * c1, hi[1] * c1);
            __half2 p1 = __floats2half2_rn(hi[2] * c1, hi[3] * c1);
            uint2 u;
            u.x = *reinterpret_cast<uint32_t*>(&p0);
            u.y = *reinterpret_cast<uint32_t*>(&p1);
            *(uint2*)&out[(size_t)g1 * HID + cb] = u;
        }
    }
}

// ---------------------------------------------------------------------------
// Readout device body: one graph, 256 threads = 128 channels x 2 phases.
// ---------------------------------------------------------------------------
__device__ __forceinline__ void readout_body(
    int g, const float* __restrict__ y, float a, float b,
    const int* __restrict__ gstart, float* __restrict__ out, int layer,
    float* s_r0, float* s_r1, float* s_r2) {
    int t = threadIdx.x;
    int c = t & 127, ph = t >> 7;
    int s0 = gstart[g], s1 = gstart[g + 1];
    float sum = 0.f, mx = -CUDART_INF_F, mn = CUDART_INF_F;
    for (int r = s0 + ph; r < s1; r += 2) {
        float v = leaky(__ldg(&y[(size_t)r * HID + c]) * a + b);
        sum += v;
        mx = fmaxf(mx, v);
        mn = fminf(mn, v);
    }
    s_r0[t] = sum; s_r1[t] = mx; s_r2[t] = mn;
    __syncthreads();
    if (ph == 0) {
        sum += s_r0[t + 128];
        mx = fmaxf(mx, s_r1[t + 128]);
        mn = fminf(mn, s_r2[t + 128]);
        int cnt = s1 - s0;
        float mean = sum / fmaxf((float)cnt, 1.f);
        if (cnt == 0) { mx = 0.f; mn = 0.f; }
        float* o = out + (size_t)g * (9 * HID) + layer * (3 * HID);
        o[c]           = leaky(mean);
        o[HID + c]     = leaky(mx);
        o[2 * HID + c] = leaky(mn);
    }
}

// ---------------------------------------------------------------------------
// Plain GEMM kernel (layer 0: no norm, no readout partner)
// ---------------------------------------------------------------------------
__global__ void __launch_bounds__(256, 2)
k_gemm0(const float* __restrict__ X, const float* __restrict__ W,
        const float* __restrict__ cs, __half* __restrict__ out) {
    __shared__ float Ws[32][HID];
    __shared__ float Xs[32][68];
    gemm_body<INF_, false>(blockIdx.x, X, W, cs, nullptr, nullptr, out, Ws, Xs);
}

// ---------------------------------------------------------------------------
// Combined kernel for layer L>=1: blocks [0,GEMM_GRID) do gemm(L) with
// norm(L-1) folded into staging; blocks [GEMM_GRID, GEMM_GRID+GG) do
// readout(L-1). Both depend only on agg(L-1); disjoint memory.
// ---------------------------------------------------------------------------
__global__ void __launch_bounds__(256, 2)
k_gemm_ro(const float* __restrict__ y, const float* __restrict__ W,
          const float* __restrict__ cs,
          const float* __restrict__ stats, const float* __restrict__ gw,
          const float* __restrict__ gb, const float* __restrict__ gs,
          __half* __restrict__ hs, const int* __restrict__ gstart,
          float* __restrict__ out, int prev_layer) {
    __shared__ float Ws[32][HID];
    __shared__ float Xs[32][68];
    __shared__ float s_a[HID], s_b[HID];

    int bid = blockIdx.x;
    if (bid < GEMM_GRID) {
        if (threadIdx.x < HID) {
            float a, b;
            alpha_beta(stats, gw, gb, gs, threadIdx.x, a, b);
            s_a[threadIdx.x] = a;
            s_b[threadIdx.x] = b;
        }
        __syncthreads();
        gemm_body<HID, true>(bid, y, W, cs, s_a, s_b, hs, Ws, Xs);
    } else {
        float a, b;
        alpha_beta(stats, gw, gb, gs, threadIdx.x & 127, a, b);
        // reuse Ws as readout scratch (3 x 256 floats fit easily)
        float* s_r0 = &Ws[0][0];
        float* s_r1 = &Ws[2][0];
        float* s_r2 = &Ws[4][0];
        readout_body(bid - GEMM_GRID, y, a, b, gstart, out, prev_layer,
                     s_r0, s_r1, s_r2);
    }
}

// ---------------------------------------------------------------------------
// Standalone readout (final layer)
// ---------------------------------------------------------------------------
__global__ void __launch_bounds__(256)
k_readout(const float* __restrict__ y, const float* __restrict__ stats,
          const float* __restrict__ gw, const float* __restrict__ gb,
          const float* __restrict__ gs, const int* __restrict__ gstart,
          float* __restrict__ out, int layer) {
    __shared__ float s_r0[256], s_r1[256], s_r2[256];
    float a, b;
    alpha_beta(stats, gw, gb, gs, threadIdx.x & 127, a, b);
    readout_body(blockIdx.x, y, a, b, gstart, out, layer, s_r0, s_r1, s_r2);
}

// ---------------------------------------------------------------------------
// TMA-bulk aggregation (round-11 proven). end = start + indeg[d].
// ---------------------------------------------------------------------------
__global__ void __launch_bounds__(256)
k_aggstats(const __half* __restrict__ hs, const int* __restrict__ csr_start,
           const int* __restrict__ indeg, const int* __restrict__ csr_src,
           const float* __restrict__ cd,
           float* __restrict__ y, float* __restrict__ stats) {
    __shared__ __align__(16) char buf[8][BUF_E * 256];   // 16 KB
    __shared__ __align__(8) uint64_t mbar[8];
    __shared__ float s_sum[8][HID];
    __shared__ float s_sq [8][HID];

    int warp = threadIdx.x >> 5, lane = threadIdx.x & 31;
    int lg = lane >> 4, li = lane & 15;
    int d = blockIdx.x * 8 + warp;
    uint32_t mb = smem_u32(&mbar[warp]);

    if (lane == 0)
        asm volatile("mbarrier.init.shared.b64 [%0], 1;" :: "r"(mb) : "memory");
    __syncwarp();

    float2 acc[4];
#pragma unroll
    for (int j = 0; j < 4; j++) acc[j] = make_float2(0.f, 0.f);

    if (d < NN) {
        int start = __ldg(&csr_start[d]);
        int end   = start + __ldg(&indeg[d]);
        uint32_t parity = 0;
        for (int i = start; i < end; i += BUF_E) {
            int cnt = min(BUF_E, end - i);
            if (lane == 0)
                asm volatile(
                    "mbarrier.arrive.expect_tx.shared.b64 _, [%0], %1;"
                    :: "r"(mb), "r"((uint32_t)(cnt * 256)) : "memory");
            __syncwarp();
            if (lane < cnt) {
                int s = __ldg(&csr_src[i + lane]);
                uint32_t dstp = smem_u32(&buf[warp][lane * 256]);
                const void* gsrc = hs + (size_t)s * HID;
                asm volatile(
                    "cp.async.bulk.shared::cluster.global.mbarrier::complete_tx::bytes "
                    "[%0], [%1], %2, [%3];"
                    :: "r"(dstp), "l"(gsrc), "r"(256u), "r"(mb) : "memory");
            }
            mbar_wait(mb, parity);
            parity ^= 1u;
            for (int j = lg; j < cnt; j += 2) {
                uint4 u = *(const uint4*)&buf[warp][j * 256 + li * 16];
                float2 f;
                f = __half22float2(*reinterpret_cast<__half2*>(&u.x));
                acc[0].x += f.x; acc[0].y += f.y;
                f = __half22float2(*reinterpret_cast<__half2*>(&u.y));
                acc[1].x += f.x; acc[1].y += f.y;
                f = __half22float2(*reinterpret_cast<__half2*>(&u.z));
                acc[2].x += f.x; acc[2].y += f.y;
                f = __half22float2(*reinterpret_cast<__half2*>(&u.w));
                acc[3].x += f.x; acc[3].y += f.y;
            }
            __syncwarp();
        }
#pragma unroll
        for (int j = 0; j < 4; j++) {
            acc[j].x += __shfl_xor_sync(0xffffffffu, acc[j].x, 16);
            acc[j].y += __shfl_xor_sync(0xffffffffu, acc[j].y, 16);
        }
        float c = __ldg(&cd[d]);
#pragma unroll
        for (int j = 0; j < 4; j++) { acc[j].x *= c; acc[j].y *= c; }
        if (lg == 0) {
            float4 o0 = make_float4(acc[0].x, acc[0].y, acc[1].x, acc[1].y);
            float4 o1 = make_float4(acc[2].x, acc[2].y, acc[3].x, acc[3].y);
            *(float4*)(y + (size_t)d * HID + li * 8)     = o0;
            *(float4*)(y + (size_t)d * HID + li * 8 + 4) = o1;
        }
    }

    if (lg == 0) {
#pragma unroll
        for (int j = 0; j < 4; j++) {
            int c0 = li * 8 + 2 * j;
            float vx = (d < NN) ? acc[j].x : 0.f;
            float vy = (d < NN) ? acc[j].y : 0.f;
            s_sum[warp][c0]     = vx;
            s_sum[warp][c0 + 1] = vy;
            s_sq [warp][c0]     = vx * vx;
            s_sq [warp][c0 + 1] = vy * vy;
        }
    }
    __syncthreads();

    int t = threadIdx.x;
    if (t < HID) {
        float s = 0.f;
#pragma unroll
        for (int w = 0; w < 8; w++) s += s_sum[w][t];
        atomicAdd(&stats[t], s);
    } else {
        int c = t - HID;
        float s = 0.f;
#pragma unroll
        for (int w = 0; w < 8; w++) s += s_sq[w][c];
        atomicAdd(&stats[HID + c], s);
    }
}

// ---------------------------------------------------------------------------
// Launch: single stream, 11 launches
// ---------------------------------------------------------------------------
extern "C" void kernel_launch(void* const* d_in, const int* in_sizes, int n_in,
                              void* d_out, int out_size) {
    const float* X   = (const float*)d_in[0];
    const float* W1  = (const float*)d_in[1];
    const float* W2  = (const float*)d_in[2];
    const float* W3  = (const float*)d_in[3];
    const float* gw  = (const float*)d_in[4];
    const float* gb  = (const float*)d_in[5];
    const float* gs  = (const float*)d_in[6];
    const int*   src = (const int*)d_in[7];
    const int*   dst = (const int*)d_in[8];
    const int*   gid = (const int*)d_in[9];
    float* out = (float*)d_out;

    __half* hs;
    float *y, *cs, *cd, *stats;
    int *deg, *gstart, *csr_start, *cursor, *csr_src, *total;
    cudaGetSymbolAddress((void**)&hs,        g_hs);
    cudaGetSymbolAddress((void**)&y,         g_y);
    cudaGetSymbolAddress((void**)&cs,        g_cs);
    cudaGetSymbolAddress((void**)&cd,        g_cd);
    cudaGetSymbolAddress((void**)&stats,     g_stats);
    cudaGetSymbolAddress((void**)&deg,       g_deg);
    cudaGetSymbolAddress((void**)&gstart,    g_gstart);
    cudaGetSymbolAddress((void**)&csr_start, g_csr_start);
    cudaGetSymbolAddress((void**)&cursor,    g_cursor);
    cudaGetSymbolAddress((void**)&csr_src,   g_csr_src);
    cudaGetSymbolAddress((void**)&total,     g_total);

    const int agg_grid  = (NN + 7) / 8;
    const int edge_grid = (EE + 255) / 256;
    int* indeg = deg + NN;

    // --- setup: 4 launches ---
    k_setup_zero<<<256, 256>>>(deg, stats, total);
    k_degrees<<<edge_grid, 256>>>(src, dst, deg);
    k_misc<<<NB_SCAN, 256>>>(deg, gid, cs, cd, gstart, csr_start, cursor, total);
    k_fill_csr<<<edge_grid, 256>>>(src, dst, cursor, csr_src);

    // --- layer 0 ---
    k_gemm0<<<GEMM_GRID, 256>>>(X, W1, cs, hs);
    k_aggstats<<<agg_grid, 256>>>(hs, csr_start, indeg, csr_src, cd, y, stats);

    // --- layer 1 gemm + layer 0 readout (combined) ---
    k_gemm_ro<<<GEMM_GRID + GG, 256>>>(y, W2, cs, stats, gw, gb, gs, hs,
                                       gstart, out, 0);
    k_aggstats<<<agg_grid, 256>>>(hs, csr_start, indeg, csr_src, cd, y,
                                  stats + 2 * HID);

    // --- layer 2 gemm + layer 1 readout (combined) ---
    k_gemm_ro<<<GEMM_GRID + GG, 256>>>(y, W3, cs, stats + 2 * HID,
                                       gw + HID, gb + HID, gs + HID, hs,
                                       gstart, out, 1);
    k_aggstats<<<agg_grid, 256>>>(hs, csr_start, indeg, csr_src, cd, y,
                                  stats + 4 * HID);

    // --- final readout ---
    k_readout<<<GG, 256>>>(y, stats + 4 * HID, gw + 2 * HID, gb + 2 * HID,
                           gs + 2 * HID, gstart, out, 2);
}

// round 14
// speedup vs baseline: 1.0989x; 1.0013x over previous
#include <cuda_runtime.h>
#include <cuda_fp16.h>
#include <math_constants.h>
#include <cstdint>

// Problem constants (fixed by the dataset)
#define NN   50000
#define EE   600000
#define GG   1000
#define HID  128
#define INF_ 64
#define EPS  1e-5f
#define SLOPE 0.01f

#define NB_SCAN ((NN + 255) / 256)    // 196
#define BUF_E 8                       // edges per TMA batch per warp
#define GEMM_GRID ((NN + 127) / 128)  // 391 (128-row blocks)

// ---------------------------------------------------------------------------
// Scratch (static __device__ arrays; no allocation anywhere)
// ---------------------------------------------------------------------------
__device__ __align__(256) __half g_hs [NN * HID];  // (x@W)*cs fp16, 256B rows
__device__ float  g_y  [NN * HID];
__device__ float  g_cs [NN];
__device__ float  g_cd [NN];
__device__ int    g_deg[2 * NN];     // [0,N): outdeg, [N,2N): indeg
__device__ int    g_csr_start[NN];   // segment base per node (non-monotonic)
__device__ int    g_cursor[NN];
__device__ int    g_csr_src[EE];
__device__ int    g_total[1];        // atomic segment allocator
__device__ float  g_stats[3 * 2 * HID];
__device__ int    g_gstart[GG + 1];

__device__ __forceinline__ float leaky(float v) { return v > 0.f ? v : SLOPE * v; }

__device__ __forceinline__ void alpha_beta(const float* __restrict__ stats,
                                           const float* __restrict__ gw,
                                           const float* __restrict__ gb,
                                           const float* __restrict__ gs,
                                           int c, float& a, float& b) {
    float m   = stats[c] * (1.f / (float)NN);
    float ex2 = stats[HID + c] * (1.f / (float)NN);
    float s   = gs[c];
    float var = ex2 - m * m * (2.f * s - s * s);
    float inv = rsqrtf(var + EPS);
    a = inv * gw[c];
    b = gb[c] - s * m * a;
}

// packed f32x2 helpers
__device__ __forceinline__ unsigned long long pack2(float x, float y) {
    unsigned long long r;
    asm("mov.b64 %0, {%1, %2};" : "=l"(r) : "f"(x), "f"(y));
    return r;
}
__device__ __forceinline__ void unpack2(unsigned long long p, float& x, float& y) {
    asm("mov.b64 {%0, %1}, %2;" : "=f"(x), "=f"(y) : "l"(p));
}
__device__ __forceinline__ void fma2(unsigned long long& d, unsigned long long a,
                                     unsigned long long b) {
    asm("fma.rn.f32x2 %0, %1, %2, %0;" : "+l"(d) : "l"(a), "l"(b));
}

__device__ __forceinline__ uint32_t smem_u32(const void* p) {
    return (uint32_t)__cvta_generic_to_shared(p);
}
__device__ __forceinline__ void mbar_wait(uint32_t mbar, uint32_t parity) {
    asm volatile(
        "{\n\t.reg .pred P1;\n\t"
        "W_%=:\n\t"
        "mbarrier.try_wait.parity.acquire.cta.shared::cta.b64 P1, [%0], %1, 0x989680;\n\t"
        "@P1 bra.uni D_%=;\n\t"
        "bra.uni W_%=;\n\t"
        "D_%=:\n\t}"
        :: "r"(mbar), "r"(parity) : "memory");
}

// ---------------------------------------------------------------------------
// Setup: zero deg + stats + segment allocator
// ---------------------------------------------------------------------------
__global__ void k_setup_zero(int* __restrict__ deg, float* __restrict__ stats,
                             int* __restrict__ total) {
    int i = blockIdx.x * blockDim.x + threadIdx.x;
    int stride = gridDim.x * blockDim.x;
    for (int j = i; j < 2 * NN; j += stride) deg[j] = 0;
    for (int j = i; j < 3 * 2 * HID; j += stride) stats[j] = 0.f;
    if (i == 0) total[0] = 0;
}

// ---------------------------------------------------------------------------
// Degrees: 4 edges per thread (int4 loads, 8 independent atomics in flight)
// ---------------------------------------------------------------------------
__global__ void k_degrees(const int* __restrict__ src, const int* __restrict__ dst,
                          int* __restrict__ deg) {
    int base = (blockIdx.x * blockDim.x + threadIdx.x) * 4;
    if (base >= EE) return;
    int4 s4 = *(const int4*)&src[base];
    int4 d4 = *(const int4*)&dst[base];
    atomicAdd(&deg[s4.x], 1);
    atomicAdd(&deg[s4.y], 1);
    atomicAdd(&deg[s4.z], 1);
    atomicAdd(&deg[s4.w], 1);
    atomicAdd(&deg[NN + d4.x], 1);
    atomicAdd(&deg[NN + d4.y], 1);
    atomicAdd(&deg[NN + d4.z], 1);
    atomicAdd(&deg[NN + d4.w], 1);
}

// ---------------------------------------------------------------------------
// Fused post-degree setup: invdeg + gstart + CSR segment assignment via
// block-local scan + one global atomicAdd (segment order irrelevant).
// ---------------------------------------------------------------------------
__global__ void k_misc(const int* __restrict__ deg, const int* __restrict__ gid,
                       float* __restrict__ cs, float* __restrict__ cd,
                       int* __restrict__ gstart, int* __restrict__ csr_start,
                       int* __restrict__ cursor, int* __restrict__ total) {
    __shared__ int sh[256];
    __shared__ int s_base;
    int t = threadIdx.x;
    int i = blockIdx.x * 256 + t;
    int v = 0;
    if (i < NN) {
        int od = deg[i], id = deg[NN + i];
        cs[i] = rsqrtf(fmaxf((float)od, 1.f));
        cd[i] = rsqrtf(fmaxf((float)id, 1.f));
        v = id;
        int g  = gid[i];
        int gp = (i == 0) ? -1 : gid[i - 1];
        for (int gg = gp + 1; gg <= g; gg++) gstart[gg] = i;
        if (i == NN - 1)
            for (int gg = g + 1; gg <= GG; gg++) gstart[gg] = NN;
    }
    sh[t] = v;
    __syncthreads();
    for (int o = 1; o < 256; o <<= 1) {
        int tv = (t >= o) ? sh[t - o] : 0;
        __syncthreads();
        sh[t] += tv;
        __syncthreads();
    }
    if (t == 255) s_base = atomicAdd(total, sh[255]);
    __syncthreads();
    if (i < NN) {
        int start = s_base + sh[t] - v;
        csr_start[i] = start;
        cursor[i] = start;
    }
}

// ---------------------------------------------------------------------------
// CSR fill: 4 edges per thread
// ---------------------------------------------------------------------------
__global__ void k_fill_csr(const int* __restrict__ src, const int* __restrict__ dst,
                           int* __restrict__ cursor, int* __restrict__ csr_src) {
    int base = (blockIdx.x * blockDim.x + threadIdx.x) * 4;
    if (base >= EE) return;
    int4 s4 = *(const int4*)&src[base];
    int4 d4 = *(const int4*)&dst[base];
    int p0 = atomicAdd(&cursor[d4.x], 1);
    int p1 = atomicAdd(&cursor[d4.y], 1);
    int p2 = atomicAdd(&cursor[d4.z], 1);
    int p3 = atomicAdd(&cursor[d4.w], 1);
    csr_src[p0] = s4.x;
    csr_src[p1] = s4.y;
    csr_src[p2] = s4.z;
    csr_src[p3] = s4.w;
}

// ---------------------------------------------------------------------------
// GEMM device body (packed f32x2): block = 128 rows x 128 cols, 8 warps,
// micro-tile 16 rows x 4 cols per thread (8 packed row-pairs).
// Per k: 32 FFMA2 + 4 broadcast LDS.128 (x) + 1 LDS.128 (w) + 4 packs.
// ---------------------------------------------------------------------------
template <int K, bool NORM>
__device__ __forceinline__ void gemm_body(
    int blk, const float* __restrict__ X, const float* __restrict__ W,
    const float* __restrict__ cs, const float* __restrict__ s_a,
    const float* __restrict__ s_b, __half* __restrict__ out,
    float (*Ws)[HID], float (*Xs)[132]) {
    int tid = threadIdx.x;
    int tx = tid & 31, ty = tid >> 5;
    int row0 = blk * 128;
    int rb = ty * 16, cb = tx * 4;

    unsigned long long acc[8][4];
#pragma unroll
    for (int i = 0; i < 8; i++)
#pragma unroll
        for (int j = 0; j < 4; j++) acc[i][j] = 0ull;

    for (int k0 = 0; k0 < K; k0 += 32) {
        for (int i = tid; i < 32 * 32; i += 256) {
            int k = i >> 5, c = (i & 31) * 4;
            *(float4*)&Ws[k][c] = *(const float4*)&W[(k0 + k) * HID + c];
        }
        for (int i = tid; i < 128 * 8; i += 256) {
            int r = i >> 3, kq = (i & 7) * 4;
            int g = row0 + r;
            float4 v = make_float4(0.f, 0.f, 0.f, 0.f);
            if (g < NN) v = *(const float4*)&X[(size_t)g * K + k0 + kq];
            if (NORM) {
                float4 a = *(const float4*)&s_a[k0 + kq];
                float4 b = *(const float4*)&s_b[k0 + kq];
                v.x = leaky(v.x * a.x + b.x);
                v.y = leaky(v.y * a.y + b.y);
                v.z = leaky(v.z * a.z + b.z);
                v.w = leaky(v.w * a.w + b.w);
            }
            Xs[kq + 0][r] = v.x;
            Xs[kq + 1][r] = v.y;
            Xs[kq + 2][r] = v.z;
            Xs[kq + 3][r] = v.w;
        }
        __syncthreads();

#pragma unroll
        for (int k = 0; k < 32; k++) {
            ulonglong2 x0 = *(const ulonglong2*)&Xs[k][rb];
            ulonglong2 x1 = *(const ulonglong2*)&Xs[k][rb + 4];
            ulonglong2 x2 = *(const ulonglong2*)&Xs[k][rb + 8];
            ulonglong2 x3 = *(const ulonglong2*)&Xs[k][rb + 12];
            float4 w = *(const float4*)&Ws[k][cb];
            unsigned long long w0 = pack2(w.x, w.x);
            unsigned long long w1 = pack2(w.y, w.y);
            unsigned long long w2 = pack2(w.z, w.z);
            unsigned long long w3 = pack2(w.w, w.w);
            fma2(acc[0][0], x0.x, w0); fma2(acc[0][1], x0.x, w1);
            fma2(acc[0][2], x0.x, w2); fma2(acc[0][3], x0.x, w3);
            fma2(acc[1][0], x0.y, w0); fma2(acc[1][1], x0.y, w1);
            fma2(acc[1][2], x0.y, w2); fma2(acc[1][3], x0.y, w3);
            fma2(acc[2][0], x1.x, w0); fma2(acc[2][1], x1.x, w1);
            fma2(acc[2][2], x1.x, w2); fma2(acc[2][3], x1.x, w3);
            fma2(acc[3][0], x1.y, w0); fma2(acc[3][1], x1.y, w1);
            fma2(acc[3][2], x1.y, w2); fma2(acc[3][3], x1.y, w3);
            fma2(acc[4][0], x2.x, w0); fma2(acc[4][1], x2.x, w1);
            fma2(acc[4][2], x2.x, w2); fma2(acc[4][3], x2.x, w3);
            fma2(acc[5][0], x2.y, w0); fma2(acc[5][1], x2.y, w1);
            fma2(acc[5][2], x2.y, w2); fma2(acc[5][3], x2.y, w3);
            fma2(acc[6][0], x3.x, w0); fma2(acc[6][1], x3.x, w1);
            fma2(acc[6][2], x3.x, w2); fma2(acc[6][3], x3.x, w3);
            fma2(acc[7][0], x3.y, w0); fma2(acc[7][1], x3.y, w1);
            fma2(acc[7][2], x3.y, w2); fma2(acc[7][3], x3.y, w3);
        }
        __syncthreads();
    }

#pragma unroll
    for (int rp = 0; rp < 8; rp++) {
        float lo[4], hi[4];
#pragma unroll
        for (int c = 0; c < 4; c++) unpack2(acc[rp][c], lo[c], hi[c]);
        int g0 = row0 + rb + 2 * rp;
        int g1 = g0 + 1;
        if (g0 < NN) {
            float c0 = __ldg(&cs[g0]);
            __half2 p0 = __floats2half2_rn(lo[0] * c0, lo[1] * c0);
            __half2 p1 = __floats2half2_rn(lo[2] * c0, lo[3] * c0);
            uint2 u;
            u.x = *reinterpret_cast<uint32_t*>(&p0);
            u.y = *reinterpret_cast<uint32_t*>(&p1);
            *(uint2*)&out[(size_t)g0 * HID + cb] = u;
        }
        if (g1 < NN) {
            float c1 = __ldg(&cs[g1]);
            __half2 p0 = __floats2half2_rn(hi[0] * c1, hi[1] * c1);
            __half2 p1 = __floats2half2_rn(hi[2] * c1, hi[3] * c1);
            uint2 u;
            u.x = *reinterpret_cast<uint32_t*>(&p0);
            u.y = *reinterpret_cast<uint32_t*>(&p1);
            *(uint2*)&out[(size_t)g1 * HID + cb] = u;
        }
    }
}

// ---------------------------------------------------------------------------
// Readout device body: one graph, 256 threads = 128 channels x 2 phases.
// ---------------------------------------------------------------------------
__device__ __forceinline__ void readout_body(
    int g, const float* __restrict__ y, float a, float b,
    const int* __restrict__ gstart, float* __restrict__ out, int layer,
    float* s_r0, float* s_r1, float* s_r2) {
    int t = threadIdx.x;
    int c = t & 127, ph = t >> 7;
    int s0 = gstart[g], s1 = gstart[g + 1];
    float sum = 0.f, mx = -CUDART_INF_F, mn = CUDART_INF_F;
    for (int r = s0 + ph; r < s1; r += 2) {
        float v = leaky(__ldg(&y[(size_t)r * HID + c]) * a + b);
        sum += v;
        mx = fmaxf(mx, v);
        mn = fminf(mn, v);
    }
    s_r0[t] = sum; s_r1[t] = mx; s_r2[t] = mn;
    __syncthreads();
    if (ph == 0) {
        sum += s_r0[t + 128];
        mx = fmaxf(mx, s_r1[t + 128]);
        mn = fminf(mn, s_r2[t + 128]);
        int cnt = s1 - s0;
        float mean = sum / fmaxf((float)cnt, 1.f);
        if (cnt == 0) { mx = 0.f; mn = 0.f; }
        float* o = out + (size_t)g * (9 * HID) + layer * (3 * HID);
        o[c]           = leaky(mean);
        o[HID + c]     = leaky(mx);
        o[2 * HID + c] = leaky(mn);
    }
}

// ---------------------------------------------------------------------------
// Layer-0 GEMM (no norm, no readout partner)
// ---------------------------------------------------------------------------
__global__ void __launch_bounds__(256, 2)
k_gemm0(const float* __restrict__ X, const float* __restrict__ W,
        const float* __restrict__ cs, __half* __restrict__ out) {
    __shared__ float Ws[32][HID];
    __shared__ float Xs[32][132];
    gemm_body<INF_, false>(blockIdx.x, X, W, cs, nullptr, nullptr, out, Ws, Xs);
}

// ---------------------------------------------------------------------------
// Combined: blocks [0,GEMM_GRID) gemm(L) w/ norm(L-1); [GEMM_GRID,+GG)
// readout(L-1). Both depend only on agg(L-1); disjoint memory. Readout
// blocks fill the gemm tail wave.
// ---------------------------------------------------------------------------
__global__ void __launch_bounds__(256, 2)
k_gemm_ro(const float* __restrict__ y, const float* __restrict__ W,
          const float* __restrict__ cs,
          const float* __restrict__ stats, const float* __restrict__ gw,
          const float* __restrict__ gb, const float* __restrict__ gs,
          __half* __restrict__ hs, const int* __restrict__ gstart,
          float* __restrict__ out, int prev_layer) {
    __shared__ float Ws[32][HID];
    __shared__ float Xs[32][132];
    __shared__ float s_a[HID], s_b[HID];

    int bid = blockIdx.x;
    if (bid < GEMM_GRID) {
        if (threadIdx.x < HID) {
            float a, b;
            alpha_beta(stats, gw, gb, gs, threadIdx.x, a, b);
            s_a[threadIdx.x] = a;
            s_b[threadIdx.x] = b;
        }
        __syncthreads();
        gemm_body<HID, true>(bid, y, W, cs, s_a, s_b, hs, Ws, Xs);
    } else {
        float a, b;
        alpha_beta(stats, gw, gb, gs, threadIdx.x & 127, a, b);
        float* s_r0 = &Ws[0][0];
        float* s_r1 = &Ws[2][0];
        float* s_r2 = &Ws[4][0];
        readout_body(bid - GEMM_GRID, y, a, b, gstart, out, prev_layer,
                     s_r0, s_r1, s_r2);
    }
}

// ---------------------------------------------------------------------------
// Standalone readout (final layer)
// ---------------------------------------------------------------------------
__global__ void __launch_bounds__(256)
k_readout(const float* __restrict__ y, const float* __restrict__ stats,
          const float* __restrict__ gw, const float* __restrict__ gb,
          const float* __restrict__ gs, const int* __restrict__ gstart,
          float* __restrict__ out, int layer) {
    __shared__ float s_r0[256], s_r1[256], s_r2[256];
    float a, b;
    alpha_beta(stats, gw, gb, gs, threadIdx.x & 127, a, b);
    readout_body(blockIdx.x, y, a, b, gstart, out, layer, s_r0, s_r1, s_r2);
}

// ---------------------------------------------------------------------------
// TMA-bulk aggregation (round-11 proven). end = start + indeg[d].
// ---------------------------------------------------------------------------
__global__ void __launch_bounds__(256)
k_aggstats(const __half* __restrict__ hs, const int* __restrict__ csr_start,
           const int* __restrict__ indeg, const int* __restrict__ csr_src,
           const float* __restrict__ cd,
           float* __restrict__ y, float* __restrict__ stats) {
    __shared__ __align__(16) char buf[8][BUF_E * 256];   // 16 KB
    __shared__ __align__(8) uint64_t mbar[8];
    __shared__ float s_sum[8][HID];
    __shared__ float s_sq [8][HID];

    int warp = threadIdx.x >> 5, lane = threadIdx.x & 31;
    int lg = lane >> 4, li = lane & 15;
    int d = blockIdx.x * 8 + warp;
    uint32_t mb = smem_u32(&mbar[warp]);

    if (lane == 0)
        asm volatile("mbarrier.init.shared.b64 [%0], 1;" :: "r"(mb) : "memory");
    __syncwarp();

    float2 acc[4];
#pragma unroll
    for (int j = 0; j < 4; j++) acc[j] = make_float2(0.f, 0.f);

    if (d < NN) {
        int start = __ldg(&csr_start[d]);
        int end   = start + __ldg(&indeg[d]);
        uint32_t parity = 0;
        for (int i = start; i < end; i += BUF_E) {
            int cnt = min(BUF_E, end - i);
            if (lane == 0)
                asm volatile(
                    "mbarrier.arrive.expect_tx.shared.b64 _, [%0], %1;"
                    :: "r"(mb), "r"((uint32_t)(cnt * 256)) : "memory");
            __syncwarp();
            if (lane < cnt) {
                int s = __ldg(&csr_src[i + lane]);
                uint32_t dstp = smem_u32(&buf[warp][lane * 256]);
                const void* gsrc = hs + (size_t)s * HID;
                asm volatile(
                    "cp.async.bulk.shared::cluster.global.mbarrier::complete_tx::bytes "
                    "[%0], [%1], %2, [%3];"
                    :: "r"(dstp), "l"(gsrc), "r"(256u), "r"(mb) : "memory");
            }
            mbar_wait(mb, parity);
            parity ^= 1u;
            for (int j = lg; j < cnt; j += 2) {
                uint4 u = *(const uint4*)&buf[warp][j * 256 + li * 16];
                float2 f;
                f = __half22float2(*reinterpret_cast<__half2*>(&u.x));
                acc[0].x += f.x; acc[0].y += f.y;
                f = __half22float2(*reinterpret_cast<__half2*>(&u.y));
                acc[1].x += f.x; acc[1].y += f.y;
                f = __half22float2(*reinterpret_cast<__half2*>(&u.z));
                acc[2].x += f.x; acc[2].y += f.y;
                f = __half22float2(*reinterpret_cast<__half2*>(&u.w));
                acc[3].x += f.x; acc[3].y += f.y;
            }
            __syncwarp();
        }
#pragma unroll
        for (int j = 0; j < 4; j++) {
            acc[j].x += __shfl_xor_sync(0xffffffffu, acc[j].x, 16);
            acc[j].y += __shfl_xor_sync(0xffffffffu, acc[j].y, 16);
        }
        float c = __ldg(&cd[d]);
#pragma unroll
        for (int j = 0; j < 4; j++) { acc[j].x *= c; acc[j].y *= c; }
        if (lg == 0) {
            float4 o0 = make_float4(acc[0].x, acc[0].y, acc[1].x, acc[1].y);
            float4 o1 = make_float4(acc[2].x, acc[2].y, acc[3].x, acc[3].y);
            *(float4*)(y + (size_t)d * HID + li * 8)     = o0;
            *(float4*)(y + (size_t)d * HID + li * 8 + 4) = o1;
        }
    }

    if (lg == 0) {
#pragma unroll
        for (int j = 0; j < 4; j++) {
            int c0 = li * 8 + 2 * j;
            float vx = (d < NN) ? acc[j].x : 0.f;
            float vy = (d < NN) ? acc[j].y : 0.f;
            s_sum[warp][c0]     = vx;
            s_sum[warp][c0 + 1] = vy;
            s_sq [warp][c0]     = vx * vx;
            s_sq [warp][c0 + 1] = vy * vy;
        }
    }
    __syncthreads();

    int t = threadIdx.x;
    if (t < HID) {
        float s = 0.f;
#pragma unroll
        for (int w = 0; w < 8; w++) s += s_sum[w][t];
        atomicAdd(&stats[t], s);
    } else {
        int c = t - HID;
        float s = 0.f;
#pragma unroll
        for (int w = 0; w < 8; w++) s += s_sq[w][c];
        atomicAdd(&stats[HID + c], s);
    }
}

// ---------------------------------------------------------------------------
// Launch: single stream, 11 launches
// ---------------------------------------------------------------------------
extern "C" void kernel_launch(void* const* d_in, const int* in_sizes, int n_in,
                              void* d_out, int out_size) {
    const float* X   = (const float*)d_in[0];
    const float* W1  = (const float*)d_in[1];
    const float* W2  = (const float*)d_in[2];
    const float* W3  = (const float*)d_in[3];
    const float* gw  = (const float*)d_in[4];
    const float* gb  = (const float*)d_in[5];
    const float* gs  = (const float*)d_in[6];
    const int*   src = (const int*)d_in[7];
    const int*   dst = (const int*)d_in[8];
    const int*   gid = (const int*)d_in[9];
    float* out = (float*)d_out;

    __half* hs;
    float *y, *cs, *cd, *stats;
    int *deg, *gstart, *csr_start, *cursor, *csr_src, *total;
    cudaGetSymbolAddress((void**)&hs,        g_hs);
    cudaGetSymbolAddress((void**)&y,         g_y);
    cudaGetSymbolAddress((void**)&cs,        g_cs);
    cudaGetSymbolAddress((void**)&cd,        g_cd);
    cudaGetSymbolAddress((void**)&stats,     g_stats);
    cudaGetSymbolAddress((void**)&deg,       g_deg);
    cudaGetSymbolAddress((void**)&gstart,    g_gstart);
    cudaGetSymbolAddress((void**)&csr_start, g_csr_start);
    cudaGetSymbolAddress((void**)&cursor,    g_cursor);
    cudaGetSymbolAddress((void**)&csr_src,   g_csr_src);
    cudaGetSymbolAddress((void**)&total,     g_total);

    const int agg_grid   = (NN + 7) / 8;
    const int edge4_grid = (EE / 4 + 255) / 256;
    int* indeg = deg + NN;

    // --- setup: 4 launches ---
    k_setup_zero<<<256, 256>>>(deg, stats, total);
    k_degrees<<<edge4_grid, 256>>>(src, dst, deg);
    k_misc<<<NB_SCAN, 256>>>(deg, gid, cs, cd, gstart, csr_start, cursor, total);
    k_fill_csr<<<edge4_grid, 256>>>(src, dst, cursor, csr_src);

    // --- layer 0 ---
    k_gemm0<<<GEMM_GRID, 256>>>(X, W1, cs, hs);
    k_aggstats<<<agg_grid, 256>>>(hs, csr_start, indeg, csr_src, cd, y, stats);

    // --- layer 1 gemm + layer 0 readout (combined) ---
    k_gemm_ro<<<GEMM_GRID + GG, 256>>>(y, W2, cs, stats, gw, gb, gs, hs,
                                       gstart, out, 0);
    k_aggstats<<<agg_grid, 256>>>(hs, csr_start, indeg, csr_src, cd, y,
                                  stats + 2 * HID);

    // --- layer 2 gemm + layer 1 readout (combined) ---
    k_gemm_ro<<<GEMM_GRID + GG, 256>>>(y, W3, cs, stats + 2 * HID,
                                       gw + HID, gb + HID, gs + HID, hs,
                                       gstart, out, 1);
    k_aggstats<<<agg_grid, 256>>>(hs, csr_start, indeg, csr_src, cd, y,
                                  stats + 4 * HID);

    // --- final readout ---
    k_readout<<<GG, 256>>>(y, stats + 4 * HID, gw + 2 * HID, gb + 2 * HID,
                           gs + 2 * HID, gstart, out, 2);
}